// round 10
// baseline (speedup 1.0000x reference)
#include <cuda_runtime.h>
#include <cuda_fp16.h>
#include <math.h>
#include <stdint.h>

// ---------------- problem constants ----------------
#define B_  4
#define N_  2048
#define C_  64
#define HS_ 512
#define H_  8
#define D_  64
#define M_  (B_*N_)
#define EPS 1e-6f
#define QSCALE 0.1803368801111144f   // log2(e)/8

#define QSZ (B_*H_*N_*D_)

// ---------------- scratch ----------------
__device__ uint8_t g_q8[QSZ];         // e4m3 [b*h][n][d], UNscaled
__device__ uint8_t g_k8[QSZ];         // e4m3
__device__ __half  g_vh[QSZ];         // fp16
__device__ __half g_wT [1536 * 64];   // WqkvT fp16 [n][k]
__device__ __half g_woT[64 * 512];
__device__ __half g_w1T[64 * 64];
__device__ __half g_w2T[64 * 64];
__device__ __half g_ctxh[M_ * HS_];   // attention output fp16 (b,n,h*64+d)

__device__ __forceinline__ uint32_t smem_u32(const void* p) {
    uint32_t a;
    asm("{ .reg .u64 t; cvta.to.shared.u64 t, %1; cvt.u32.u64 %0, t; }" : "=r"(a) : "l"(p));
    return a;
}
__device__ __forceinline__ void mma16816(float c[4], const uint32_t a[4],
                                         uint32_t b0, uint32_t b1) {
    asm volatile("mma.sync.aligned.m16n8k16.row.col.f32.f16.f16.f32 "
        "{%0,%1,%2,%3}, {%4,%5,%6,%7}, {%8,%9}, {%0,%1,%2,%3};"
        : "+f"(c[0]), "+f"(c[1]), "+f"(c[2]), "+f"(c[3])
        : "r"(a[0]), "r"(a[1]), "r"(a[2]), "r"(a[3]), "r"(b0), "r"(b1));
}
// fp8 QMMA: D(16x8,f32) += A(16x32,e4m3) * B(32x8,e4m3)
__device__ __forceinline__ void mma16832f8(float c[4], const uint32_t a[4],
                                           uint32_t b0, uint32_t b1) {
    asm volatile("mma.sync.aligned.m16n8k32.row.col.f32.e4m3.e4m3.f32 "
        "{%0,%1,%2,%3}, {%4,%5,%6,%7}, {%8,%9}, {%0,%1,%2,%3};"
        : "+f"(c[0]), "+f"(c[1]), "+f"(c[2]), "+f"(c[3])
        : "r"(a[0]), "r"(a[1]), "r"(a[2]), "r"(a[3]), "r"(b0), "r"(b1));
}
__device__ __forceinline__ void ldm_x4(uint32_t r[4], uint32_t addr) {
    asm volatile("ldmatrix.sync.aligned.m8n8.x4.shared.b16 {%0,%1,%2,%3}, [%4];"
        : "=r"(r[0]), "=r"(r[1]), "=r"(r[2]), "=r"(r[3]) : "r"(addr));
}
__device__ __forceinline__ void ldm_x4_t(uint32_t r[4], uint32_t addr) {
    asm volatile("ldmatrix.sync.aligned.m8n8.x4.trans.shared.b16 {%0,%1,%2,%3}, [%4];"
        : "=r"(r[0]), "=r"(r[1]), "=r"(r[2]), "=r"(r[3]) : "r"(addr));
}
__device__ __forceinline__ uint32_t exp2_pack(float lo, float hi) {
    uint32_t r;
    asm("cvt.rn.f16x2.f32 %0, %1, %2;" : "=r"(r) : "f"(hi), "f"(lo));
    asm("ex2.approx.f16x2 %0, %0;" : "+r"(r));
    return r;
}
__device__ __forceinline__ uint16_t to_e4m3x2(float lo, float hi) {
    uint16_t r;   // high byte = hi, low byte = lo
    asm("cvt.rn.satfinite.e4m3x2.f32 %0, %1, %2;" : "=h"(r) : "f"(hi), "f"(lo));
    return r;
}
__device__ __forceinline__ void cpa16(uint32_t dst, const void* src) {
    asm volatile("cp.async.ca.shared.global [%0], [%1], 16;" :: "r"(dst), "l"(src) : "memory");
}
__device__ __forceinline__ float gelu(float v) {
    return 0.5f * v * (1.0f + erff(v * 0.70710678118f));
}

// =====================================================================
// Kernel 0: all weight prep (fp32 -> fp16 transposed)
// =====================================================================
__global__ __launch_bounds__(256) void wt_kernel(
    const float* __restrict__ Wqkv, const float* __restrict__ Wout,
    const float* __restrict__ W1, const float* __restrict__ W2)
{
    int idx = blockIdx.x * 256 + threadIdx.x;   // 139264 total
    if (idx < 98304) {
        int k = idx / 1536, n = idx - k * 1536;
        g_wT[n * 64 + k] = __float2half(Wqkv[idx]);
    } else if (idx < 131072) {
        int i = idx - 98304; int k = i >> 6, n = i & 63;
        g_woT[n * 512 + k] = __float2half(Wout[i]);
    } else if (idx < 135168) {
        int i = idx - 131072; int k = i >> 6, n = i & 63;
        g_w1T[n * 64 + k] = __float2half(W1[i]);
    } else {
        int i = idx - 135168; int k = i >> 6, n = i & 63;
        g_w2T[n * 64 + k] = __float2half(W2[i]);
    }
}

// =====================================================================
// Kernel 1: LN1 + QKV GEMM (fp16 mma); q,k stored e4m3, v fp16.
// grid 128 m-tiles, 128 threads.
// =====================================================================
__global__ __launch_bounds__(128) void ln_qkv_kernel(
    const float* __restrict__ x, const float* __restrict__ g1,
    const float* __restrict__ be1, const float* __restrict__ bias)
{
    __shared__ __align__(16) uint32_t Ys[64 * 36];
    __shared__ __align__(16) uint32_t Ws[2][128 * 36];

    const int tid = threadIdx.x, wid = tid >> 5, lane = tid & 31;
    const int qr = lane >> 2, qc = lane & 3;
    const int m0 = blockIdx.x * 64;
    const uint32_t* wtw = (const uint32_t*)g_wT;

    auto issueW = [&](int jt, int buf) {
#pragma unroll
        for (int it = 0; it < 8; it++) {
            int cid = tid + 128 * it;               // 1024 chunks of 16B
            int row = cid >> 3, cc = cid & 7;
            cpa16(smem_u32(&Ws[buf][row * 36 + cc * 4]),
                  wtw + (jt * 128 + row) * 32 + cc * 4);
        }
        asm volatile("cp.async.commit_group;" ::: "memory");
    };
    issueW(0, 0);

    {
        const float g1a = g1[lane], g1b = g1[lane + 32];
        const float bea = be1[lane], beb = be1[lane + 32];
        __half* ysh = (__half*)Ys;
#pragma unroll
        for (int rr = 0; rr < 16; rr++) {
            int row = wid * 16 + rr;
            float a = x[(m0 + row) * 64 + lane];
            float b = x[(m0 + row) * 64 + lane + 32];
            float s = a + b;
#pragma unroll
            for (int o = 16; o; o >>= 1) s += __shfl_xor_sync(0xffffffffu, s, o);
            float mean = s * (1.0f / 64.0f);
            float da = a - mean, db = b - mean;
            float q = da * da + db * db;
#pragma unroll
            for (int o = 16; o; o >>= 1) q += __shfl_xor_sync(0xffffffffu, q, o);
            float rstd = rsqrtf(q * (1.0f / 64.0f) + EPS);
            ysh[row * 72 + lane]      = __float2half(da * rstd * g1a + bea);
            ysh[row * 72 + lane + 32] = __float2half(db * rstd * g1b + beb);
        }
    }
    __syncthreads();

    const uint32_t ys_base = smem_u32(Ys);
    uint32_t a[4][4][4];
#pragma unroll
    for (int m = 0; m < 4; m++)
#pragma unroll
        for (int kc = 0; kc < 4; kc++)
            ldm_x4(a[m][kc], ys_base + (m * 16 + (lane & 15)) * 144
                              + (kc * 16 + (lane >> 4) * 8) * 2);

    for (int jt = 0; jt < 12; jt++) {
        const int buf = jt & 1;
        asm volatile("cp.async.wait_group 0;" ::: "memory");
        __syncthreads();
        if (jt < 11) issueW(jt + 1, buf ^ 1);

        const uint32_t ws_base = smem_u32(&Ws[buf][0]);
        float c[4][4][4] = {};
#pragma unroll
        for (int kcp = 0; kcp < 2; kcp++) {
#pragma unroll
            for (int nb = 0; nb < 4; nb++) {
                uint32_t b[4];
                ldm_x4(b, ws_base + (wid * 32 + nb * 8 + (lane & 7)) * 144
                              + (kcp * 32 + (lane >> 3) * 8) * 2);
#pragma unroll
                for (int m = 0; m < 4; m++) {
                    mma16816(c[m][nb], a[m][2 * kcp],     b[0], b[1]);
                    mma16816(c[m][nb], a[m][2 * kcp + 1], b[2], b[3]);
                }
            }
        }
        const int j0 = jt * 128;
#pragma unroll
        for (int nb = 0; nb < 4; nb++) {
            int j = j0 + wid * 32 + nb * 8 + qc * 2;
            int sel = j >> 9, head = (j >> 6) & 7, d = j & 63;
            float bj0 = bias[j], bj1 = bias[j + 1];
#pragma unroll
            for (int m = 0; m < 4; m++) {
#pragma unroll
                for (int hf = 0; hf < 2; hf++) {
                    int gm = m0 + m * 16 + qr + hf * 8;
                    int bi = gm >> 11, n = gm & 2047;
                    float v0 = c[m][nb][hf * 2]     + bj0;
                    float v1 = c[m][nb][hf * 2 + 1] + bj1;
                    size_t off = ((size_t)(bi * 8 + head) * 2048 + n) * 64 + d;
                    if (sel == 2) {
                        *(__half2*)(g_vh + off) = __floats2half2_rn(v0, v1);
                    } else {
                        uint8_t* dst8 = (sel == 0) ? g_q8 : g_k8;
                        *(uint16_t*)(dst8 + off) = to_e4m3x2(v0, v1);
                    }
                }
            }
        }
    }
}

// =====================================================================
// Kernel 2: flash attention. 64 q-rows / 4 warps / 128 threads (proven
// config). S-phase in fp8 (m16n8k32 e4m3), P.V in fp16.
// smem: Qs8 64x80B | K8[2] 64x80B | Vh[2] 64x144B (ones-extended)
// =====================================================================
__global__ __launch_bounds__(128) void attn_kernel()
{
    __shared__ __align__(16) uint32_t Qs8[64 * 20];       // 5120 B
    __shared__ __align__(16) uint32_t K8s[2][64 * 20];    // 2x5120 B
    __shared__ __align__(16) uint32_t Vhs[2][64 * 36];    // 2x9216 B

    const int tid = threadIdx.x, wid = tid >> 5, lane = tid & 31;
    const int qr = lane >> 2, qc = lane & 3;
    const int bh = blockIdx.y, q0 = blockIdx.x * 64;
    const uint32_t* qb = (const uint32_t*)(g_q8 + (size_t)bh * N_ * D_);
    const uint8_t* kb8 = g_k8 + (size_t)bh * N_ * D_;
    const __half* vbh = g_vh + (size_t)bh * N_ * D_;

    // stage Q (64 rows x 16 words, row stride 20 words)
#pragma unroll
    for (int r = 0; r < 8; r++) {
        int idx = tid + 128 * r; int row = idx >> 4, w = idx & 15;
        Qs8[row * 20 + w] = qb[(q0 + row) * 16 + w];
    }
    // V ones-extension: words 32..35 of 64 rows x 2 buffers
#pragma unroll
    for (int r = 0; r < 4; r++) {
        int idx = tid + 128 * r;                   // 0..511
        int buf = idx >> 8, row = (idx >> 2) & 63, w = 32 + (idx & 3);
        Vhs[buf][row * 36 + w] = (w == 32) ? 0x00003C00u : 0u;
    }

    auto issue = [&](int kt, int buf) {
        // K fp8: 64 rows x 4 chunks = 256
#pragma unroll
        for (int it = 0; it < 2; it++) {
            int cid = tid + 128 * it;
            int row = cid >> 2, cc = cid & 3;
            cpa16(smem_u32(&K8s[buf][row * 20 + cc * 4]),
                  kb8 + (size_t)(kt * 64 + row) * 64 + cc * 16);
        }
        // V fp16: 64 rows x 8 chunks = 512
#pragma unroll
        for (int it = 0; it < 4; it++) {
            int cid = tid + 128 * it;
            int row = cid >> 3, cc = cid & 7;
            cpa16(smem_u32(&Vhs[buf][row * 36 + cc * 4]),
                  vbh + (size_t)(kt * 64 + row) * 64 + cc * 8);
        }
        asm volatile("cp.async.commit_group;" ::: "memory");
    };
    issue(0, 0);
    __syncthreads();

    // Q fp8 A-fragments: aq8[kc][4] for kc = 32-wide d-chunk
    const uint32_t q_base = smem_u32(Qs8);
    uint32_t aq8[2][4];
    {
        uint32_t addr = q_base + (wid * 16 + (lane & 15)) * 80 + (lane >> 4) * 16;
        ldm_x4(aq8[0], addr);
        ldm_x4(aq8[1], addr + 32);
    }

    float oacc[9][4] = {};   // [0..7]=O d-blocks, [8]=row-sum (ones col)

    for (int kt = 0; kt < 32; kt++) {
        const int buf = kt & 1;
        asm volatile("cp.async.wait_group 0;" ::: "memory");
        __syncthreads();
        if (kt < 31) issue(kt + 1, buf ^ 1);

        const uint32_t Kbase = smem_u32(&K8s[buf][0]);
        const uint32_t Vbase = smem_u32(&Vhs[buf][0]);

        // S = Q @ K^T in fp8: per nb one ldm_x4 covers full k=0..63
        float sacc[8][4] = {};
#pragma unroll
        for (int nb = 0; nb < 8; nb++) {
            uint32_t b[4];
            ldm_x4(b, Kbase + (nb * 8 + (lane & 7)) * 80 + (lane >> 3) * 16);
            mma16832f8(sacc[nb], aq8[0], b[0], b[1]);
            mma16832f8(sacc[nb], aq8[1], b[2], b[3]);
        }

        // scale by log2e/8, P = 2^S packed f16x2
        uint32_t ap[4][4];
#pragma unroll
        for (int j = 0; j < 4; j++) {
            ap[j][0] = exp2_pack(sacc[2 * j][0] * QSCALE,     sacc[2 * j][1] * QSCALE);
            ap[j][1] = exp2_pack(sacc[2 * j][2] * QSCALE,     sacc[2 * j][3] * QSCALE);
            ap[j][2] = exp2_pack(sacc[2 * j + 1][0] * QSCALE, sacc[2 * j + 1][1] * QSCALE);
            ap[j][3] = exp2_pack(sacc[2 * j + 1][2] * QSCALE, sacc[2 * j + 1][3] * QSCALE);
        }

        // O += P @ V (fp16), nb=8 = ones column (row sums)
#pragma unroll
        for (int nb = 0; nb < 9; nb++) {
#pragma unroll
            for (int kcp = 0; kcp < 2; kcp++) {
                uint32_t b[4];
                uint32_t row = kcp * 32 + (lane & 7) + (lane >> 3) * 8;
                ldm_x4_t(b, Vbase + row * 144 + nb * 16);
                mma16816(oacc[nb], ap[2 * kcp],     b[0], b[1]);
                mma16816(oacc[nb], ap[2 * kcp + 1], b[2], b[3]);
            }
        }
    }

    const float lsum0 = __shfl_sync(0xffffffffu, oacc[8][0], lane & 28);
    const float lsum1 = __shfl_sync(0xffffffffu, oacc[8][2], lane & 28);
    const float inv0 = 1.0f / lsum0, inv1 = 1.0f / lsum1;

    const int bi = bh >> 3, head = bh & 7;
    const int n0 = q0 + wid * 16 + qr;
#pragma unroll
    for (int nb = 0; nb < 8; nb++) {
        const int d = nb * 8 + qc * 2;
        *(__half2*)(g_ctxh + ((size_t)(bi * 2048 + n0)) * 512 + head * 64 + d) =
            __floats2half2_rn(oacc[nb][0] * inv0, oacc[nb][1] * inv0);
        *(__half2*)(g_ctxh + ((size_t)(bi * 2048 + n0 + 8)) * 512 + head * 64 + d) =
            __floats2half2_rn(oacc[nb][2] * inv1, oacc[nb][3] * inv1);
    }
}

// =====================================================================
// Kernel 3: FUSED outproj+GELU+res -> LN2 -> MLP+GELU -> +res -> out.
// =====================================================================
#define FUSED_SMEM 53248

__global__ __launch_bounds__(256) void fused_tail_kernel(
    const float* __restrict__ x, const float* __restrict__ bout,
    const float* __restrict__ g2, const float* __restrict__ be2,
    const float* __restrict__ b1, const float* __restrict__ b2,
    float* __restrict__ out)
{
    extern __shared__ __align__(16) unsigned char dynsm[];
    uint32_t* smw = (uint32_t*)dynsm;
    float* x2s = (float*)(dynsm + 36864);
    const uint32_t base = smem_u32(dynsm);
    const uint32_t ctxs_b = base, wos_b = base + 17408;
    const uint32_t y2s_b = base, hs_b = base + 9216;
    const uint32_t w1s_b = base + 18432, w2s_b = base + 27648;

    const int tid = threadIdx.x, wid = tid >> 5, lane = tid & 31;
    const int qr = lane >> 2, qc = lane & 3;
    const int mb = wid & 3, nhalf = wid >> 2;
    const int m0 = blockIdx.x * 64;

    float c[4][4] = {};
    for (int kc = 0; kc < 4; kc++) {
        __syncthreads();
#pragma unroll
        for (int it = 0; it < 4; it++) {
            int cid = tid + 256 * it;
            int row = cid >> 4, cc = cid & 15;
            cpa16(ctxs_b + (row * 68 + cc * 4) * 4,
                  g_ctxh + (size_t)(m0 + row) * 512 + kc * 128 + cc * 8);
        }
#pragma unroll
        for (int it = 0; it < 4; it++) {
            int cid = tid + 256 * it;
            int row = cid >> 4, cc = cid & 15;
            cpa16(wos_b + (row * 68 + cc * 4) * 4,
                  g_woT + (size_t)row * 512 + kc * 128 + cc * 8);
        }
        asm volatile("cp.async.commit_group;" ::: "memory");
        asm volatile("cp.async.wait_group 0;" ::: "memory");
        __syncthreads();

#pragma unroll
        for (int kp = 0; kp < 4; kp++) {
            uint32_t a0[4], a1[4];
            uint32_t arow = ctxs_b + (mb * 16 + (lane & 15)) * 272
                            + (kp * 32 + (lane >> 4) * 8) * 2;
            ldm_x4(a0, arow);
            ldm_x4(a1, arow + 32);
#pragma unroll
            for (int nb = 0; nb < 4; nb++) {
                uint32_t b[4];
                ldm_x4(b, wos_b + (nhalf * 32 + nb * 8 + (lane & 7)) * 272
                              + (kp * 32 + (lane >> 3) * 8) * 2);
                mma16816(c[nb], a0, b[0], b[1]);
                mma16816(c[nb], a1, b[2], b[3]);
            }
        }
    }
#pragma unroll
    for (int nb = 0; nb < 4; nb++) {
        int col = nhalf * 32 + nb * 8 + qc * 2;
        float bj0 = bout[col], bj1 = bout[col + 1];
#pragma unroll
        for (int hf = 0; hf < 2; hf++) {
            int row = mb * 16 + qr + hf * 8;
            float xv0 = x[(m0 + row) * 64 + col];
            float xv1 = x[(m0 + row) * 64 + col + 1];
            x2s[row * 64 + col]     = gelu(c[nb][hf * 2]     + bj0) + xv0;
            x2s[row * 64 + col + 1] = gelu(c[nb][hf * 2 + 1] + bj1) + xv1;
        }
    }
    __syncthreads();

    {
        const float g2a = g2[lane], g2b = g2[lane + 32];
        const float bea = be2[lane], beb = be2[lane + 32];
        __half* ysh = (__half*)dynsm;
#pragma unroll
        for (int rr = 0; rr < 8; rr++) {
            int row = wid * 8 + rr;
            float a = x2s[row * 64 + lane], b = x2s[row * 64 + lane + 32];
            float s = a + b;
#pragma unroll
            for (int o = 16; o; o >>= 1) s += __shfl_xor_sync(0xffffffffu, s, o);
            float mean = s * (1.0f / 64.0f);
            float da = a - mean, db = b - mean;
            float q = da * da + db * db;
#pragma unroll
            for (int o = 16; o; o >>= 1) q += __shfl_xor_sync(0xffffffffu, q, o);
            float rstd = rsqrtf(q * (1.0f / 64.0f) + EPS);
            ysh[row * 72 + lane]      = __float2half(da * rstd * g2a + bea);
            ysh[row * 72 + lane + 32] = __float2half(db * rstd * g2b + beb);
        }
    }
#pragma unroll
    for (int it = 0; it < 8; it++) {
        int cid = tid + 256 * it;
        int row = cid >> 5, w = cid & 31;
        smw[(w1s_b - base) / 4 + row * 36 + w] = ((const uint32_t*)g_w1T)[cid];
        smw[(w2s_b - base) / 4 + row * 36 + w] = ((const uint32_t*)g_w2T)[cid];
    }
    __syncthreads();

    float c2[4][4] = {};
#pragma unroll
    for (int kp = 0; kp < 2; kp++) {
        uint32_t a0[4], a1[4];
        uint32_t arow = y2s_b + (mb * 16 + (lane & 15)) * 144
                        + (kp * 32 + (lane >> 4) * 8) * 2;
        ldm_x4(a0, arow);
        ldm_x4(a1, arow + 32);
#pragma unroll
        for (int nb = 0; nb < 4; nb++) {
            uint32_t b[4];
            ldm_x4(b, w1s_b + (nhalf * 32 + nb * 8 + (lane & 7)) * 144
                          + (kp * 32 + (lane >> 3) * 8) * 2);
            mma16816(c2[nb], a0, b[0], b[1]);
            mma16816(c2[nb], a1, b[2], b[3]);
        }
    }
    {
        __half* hsh = (__half*)(dynsm + 9216);
#pragma unroll
        for (int nb = 0; nb < 4; nb++) {
            int col = nhalf * 32 + nb * 8 + qc * 2;
            float bj0 = b1[col], bj1 = b1[col + 1];
#pragma unroll
            for (int hf = 0; hf < 2; hf++) {
                int row = mb * 16 + qr + hf * 8;
                *(__half2*)(hsh + row * 72 + col) = __floats2half2_rn(
                    gelu(c2[nb][hf * 2] + bj0), gelu(c2[nb][hf * 2 + 1] + bj1));
            }
        }
    }
    __syncthreads();

    float c3[4][4] = {};
#pragma unroll
    for (int kp = 0; kp < 2; kp++) {
        uint32_t a0[4], a1[4];
        uint32_t arow = hs_b + (mb * 16 + (lane & 15)) * 144
                        + (kp * 32 + (lane >> 4) * 8) * 2;
        ldm_x4(a0, arow);
        ldm_x4(a1, arow + 32);
#pragma unroll
        for (int nb = 0; nb < 4; nb++) {
            uint32_t b[4];
            ldm_x4(b, w2s_b + (nhalf * 32 + nb * 8 + (lane & 7)) * 144
                          + (kp * 32 + (lane >> 3) * 8) * 2);
            mma16816(c3[nb], a0, b[0], b[1]);
            mma16816(c3[nb], a1, b[2], b[3]);
        }
    }
#pragma unroll
    for (int nb = 0; nb < 4; nb++) {
        int col = nhalf * 32 + nb * 8 + qc * 2;
        float bj0 = b2[col], bj1 = b2[col + 1];
#pragma unroll
        for (int hf = 0; hf < 2; hf++) {
            int row = mb * 16 + qr + hf * 8;
            out[(m0 + row) * 64 + col]     = c3[nb][hf * 2]     + bj0 + x2s[row * 64 + col];
            out[(m0 + row) * 64 + col + 1] = c3[nb][hf * 2 + 1] + bj1 + x2s[row * 64 + col + 1];
        }
    }
}

// =====================================================================
extern "C" void kernel_launch(void* const* d_in, const int* in_sizes, int n_in,
                              void* d_out, int out_size)
{
    const float* x    = (const float*)d_in[0];
    const float* g1   = (const float*)d_in[1];
    const float* be1  = (const float*)d_in[2];
    const float* Wqkv = (const float*)d_in[3];
    const float* bqkv = (const float*)d_in[4];
    const float* Wout = (const float*)d_in[5];
    const float* bout = (const float*)d_in[6];
    const float* g2   = (const float*)d_in[7];
    const float* be2  = (const float*)d_in[8];
    const float* W1   = (const float*)d_in[9];
    const float* b1   = (const float*)d_in[10];
    const float* W2   = (const float*)d_in[11];
    const float* b2   = (const float*)d_in[12];
    float* out = (float*)d_out;

    cudaFuncSetAttribute(fused_tail_kernel,
                         cudaFuncAttributeMaxDynamicSharedMemorySize, FUSED_SMEM);

    wt_kernel<<<544, 256>>>(Wqkv, Wout, W1, W2);
    ln_qkv_kernel<<<128, 128>>>(x, g1, be1, bqkv);
    attn_kernel<<<dim3(32, 32), 128>>>();
    fused_tail_kernel<<<128, 256, FUSED_SMEM>>>(x, bout, g2, be2, b1, b2, out);
}

// round 11
// speedup vs baseline: 1.1288x; 1.1288x over previous
#include <cuda_runtime.h>
#include <cuda_fp16.h>
#include <math.h>
#include <stdint.h>

// ---------------- problem constants ----------------
#define B_  4
#define N_  2048
#define C_  64
#define HS_ 512
#define H_  8
#define D_  64
#define M_  (B_*N_)
#define EPS 1e-6f
#define QSCALE 0.1803368801111144f   // log2(e)/8

#define QSZ (B_*H_*N_*D_)

// ---------------- scratch ----------------
__device__ __half g_qh[QSZ];          // [b*h][n][d], pre-scaled log2e/8
__device__ __half g_kh[QSZ];
__device__ __half g_vh[QSZ];
__device__ __half g_wT [1536 * 64];   // WqkvT fp16 [n][k]
__device__ __half g_woT[64 * 512];
__device__ __half g_w1T[64 * 64];
__device__ __half g_w2T[64 * 64];
__device__ __half g_ctxh[M_ * HS_];   // attention output fp16 (b,n,h*64+d)

__device__ __forceinline__ uint32_t smem_u32(const void* p) {
    uint32_t a;
    asm("{ .reg .u64 t; cvta.to.shared.u64 t, %1; cvt.u32.u64 %0, t; }" : "=r"(a) : "l"(p));
    return a;
}
__device__ __forceinline__ void mma16816(float c[4], const uint32_t a[4],
                                         uint32_t b0, uint32_t b1) {
    asm volatile("mma.sync.aligned.m16n8k16.row.col.f32.f16.f16.f32 "
        "{%0,%1,%2,%3}, {%4,%5,%6,%7}, {%8,%9}, {%0,%1,%2,%3};"
        : "+f"(c[0]), "+f"(c[1]), "+f"(c[2]), "+f"(c[3])
        : "r"(a[0]), "r"(a[1]), "r"(a[2]), "r"(a[3]), "r"(b0), "r"(b1));
}
// f16-accumulator HMMA: C(16x8,f16x2 pair) += A(16x16,f16) * B(16x8,f16)
__device__ __forceinline__ void mma16816h(uint32_t c[2], const uint32_t a[4],
                                          uint32_t b0, uint32_t b1) {
    asm volatile("mma.sync.aligned.m16n8k16.row.col.f16.f16.f16.f16 "
        "{%0,%1}, {%2,%3,%4,%5}, {%6,%7}, {%0,%1};"
        : "+r"(c[0]), "+r"(c[1])
        : "r"(a[0]), "r"(a[1]), "r"(a[2]), "r"(a[3]), "r"(b0), "r"(b1));
}
__device__ __forceinline__ void ldm_x4(uint32_t r[4], uint32_t addr) {
    asm volatile("ldmatrix.sync.aligned.m8n8.x4.shared.b16 {%0,%1,%2,%3}, [%4];"
        : "=r"(r[0]), "=r"(r[1]), "=r"(r[2]), "=r"(r[3]) : "r"(addr));
}
__device__ __forceinline__ void ldm_x4_t(uint32_t r[4], uint32_t addr) {
    asm volatile("ldmatrix.sync.aligned.m8n8.x4.trans.shared.b16 {%0,%1,%2,%3}, [%4];"
        : "=r"(r[0]), "=r"(r[1]), "=r"(r[2]), "=r"(r[3]) : "r"(addr));
}
__device__ __forceinline__ uint32_t ex2h2(uint32_t x) {
    asm("ex2.approx.f16x2 %0, %0;" : "+r"(x));
    return x;
}
__device__ __forceinline__ void cpa16(uint32_t dst, const void* src) {
    asm volatile("cp.async.ca.shared.global [%0], [%1], 16;" :: "r"(dst), "l"(src) : "memory");
}
__device__ __forceinline__ float gelu(float v) {
    return 0.5f * v * (1.0f + erff(v * 0.70710678118f));
}

// =====================================================================
// Kernel 0: all weight prep (fp32 -> fp16 transposed)
// =====================================================================
__global__ __launch_bounds__(256) void wt_kernel(
    const float* __restrict__ Wqkv, const float* __restrict__ Wout,
    const float* __restrict__ W1, const float* __restrict__ W2)
{
    int idx = blockIdx.x * 256 + threadIdx.x;   // 139264 total
    if (idx < 98304) {
        int k = idx / 1536, n = idx - k * 1536;
        g_wT[n * 64 + k] = __float2half(Wqkv[idx]);
    } else if (idx < 131072) {
        int i = idx - 98304; int k = i >> 6, n = i & 63;
        g_woT[n * 512 + k] = __float2half(Wout[i]);
    } else if (idx < 135168) {
        int i = idx - 131072; int k = i >> 6, n = i & 63;
        g_w1T[n * 64 + k] = __float2half(W1[i]);
    } else {
        int i = idx - 135168; int k = i >> 6, n = i & 63;
        g_w2T[n * 64 + k] = __float2half(W2[i]);
    }
}

// =====================================================================
// Kernel 1: LN1 + QKV GEMM (fp16 mma). grid 128 m-tiles, 128 threads.
// =====================================================================
__global__ __launch_bounds__(128) void ln_qkv_kernel(
    const float* __restrict__ x, const float* __restrict__ g1,
    const float* __restrict__ be1, const float* __restrict__ bias)
{
    __shared__ __align__(16) uint32_t Ys[64 * 36];
    __shared__ __align__(16) uint32_t Ws[2][128 * 36];

    const int tid = threadIdx.x, wid = tid >> 5, lane = tid & 31;
    const int qr = lane >> 2, qc = lane & 3;
    const int m0 = blockIdx.x * 64;
    const uint32_t* wtw = (const uint32_t*)g_wT;

    auto issueW = [&](int jt, int buf) {
#pragma unroll
        for (int it = 0; it < 8; it++) {
            int cid = tid + 128 * it;               // 1024 chunks of 16B
            int row = cid >> 3, cc = cid & 7;
            cpa16(smem_u32(&Ws[buf][row * 36 + cc * 4]),
                  wtw + (jt * 128 + row) * 32 + cc * 4);
        }
        asm volatile("cp.async.commit_group;" ::: "memory");
    };
    issueW(0, 0);

    {
        const float g1a = g1[lane], g1b = g1[lane + 32];
        const float bea = be1[lane], beb = be1[lane + 32];
        __half* ysh = (__half*)Ys;
#pragma unroll
        for (int rr = 0; rr < 16; rr++) {
            int row = wid * 16 + rr;
            float a = x[(m0 + row) * 64 + lane];
            float b = x[(m0 + row) * 64 + lane + 32];
            float s = a + b;
#pragma unroll
            for (int o = 16; o; o >>= 1) s += __shfl_xor_sync(0xffffffffu, s, o);
            float mean = s * (1.0f / 64.0f);
            float da = a - mean, db = b - mean;
            float q = da * da + db * db;
#pragma unroll
            for (int o = 16; o; o >>= 1) q += __shfl_xor_sync(0xffffffffu, q, o);
            float rstd = rsqrtf(q * (1.0f / 64.0f) + EPS);
            ysh[row * 72 + lane]      = __float2half(da * rstd * g1a + bea);
            ysh[row * 72 + lane + 32] = __float2half(db * rstd * g1b + beb);
        }
    }
    __syncthreads();

    const uint32_t ys_base = smem_u32(Ys);
    uint32_t a[4][4][4];
#pragma unroll
    for (int m = 0; m < 4; m++)
#pragma unroll
        for (int kc = 0; kc < 4; kc++)
            ldm_x4(a[m][kc], ys_base + (m * 16 + (lane & 15)) * 144
                              + (kc * 16 + (lane >> 4) * 8) * 2);

    for (int jt = 0; jt < 12; jt++) {
        const int buf = jt & 1;
        asm volatile("cp.async.wait_group 0;" ::: "memory");
        __syncthreads();
        if (jt < 11) issueW(jt + 1, buf ^ 1);

        const uint32_t ws_base = smem_u32(&Ws[buf][0]);
        float c[4][4][4] = {};
#pragma unroll
        for (int kcp = 0; kcp < 2; kcp++) {
#pragma unroll
            for (int nb = 0; nb < 4; nb++) {
                uint32_t b[4];
                ldm_x4(b, ws_base + (wid * 32 + nb * 8 + (lane & 7)) * 144
                              + (kcp * 32 + (lane >> 3) * 8) * 2);
#pragma unroll
                for (int m = 0; m < 4; m++) {
                    mma16816(c[m][nb], a[m][2 * kcp],     b[0], b[1]);
                    mma16816(c[m][nb], a[m][2 * kcp + 1], b[2], b[3]);
                }
            }
        }
        const int j0 = jt * 128;
#pragma unroll
        for (int nb = 0; nb < 4; nb++) {
            int j = j0 + wid * 32 + nb * 8 + qc * 2;
            int sel = j >> 9, head = (j >> 6) & 7, d = j & 63;
            float bj0 = bias[j], bj1 = bias[j + 1];
            float sc = (sel == 0) ? QSCALE : 1.0f;
            __half* dst = (sel == 0) ? g_qh : (sel == 1) ? g_kh : g_vh;
#pragma unroll
            for (int m = 0; m < 4; m++) {
#pragma unroll
                for (int hf = 0; hf < 2; hf++) {
                    int gm = m0 + m * 16 + qr + hf * 8;
                    int bi = gm >> 11, n = gm & 2047;
                    float v0 = (c[m][nb][hf * 2]     + bj0) * sc;
                    float v1 = (c[m][nb][hf * 2 + 1] + bj1) * sc;
                    size_t off = ((size_t)(bi * 8 + head) * 2048 + n) * 64 + d;
                    *(__half2*)(dst + off) = __floats2half2_rn(v0, v1);
                }
            }
        }
    }
}

// =====================================================================
// Kernel 2: flash attention, 64 q-rows / 4 warps / 128 threads.
// S-phase in f16-accum HMMA; ex2.approx.f16x2 applied IN PLACE on the
// accumulator regs, which then serve directly as P A-fragments (the
// f16 C-fragment layout == A-fragment layout). Row sums via __hadd2
// per tile + fp32 across tiles (ones-column removed).
// =====================================================================
__global__ __launch_bounds__(128) void attn_kernel()
{
    __shared__ __align__(16) uint32_t Qs[64 * 36];
    __shared__ __align__(16) uint32_t KV[2][2][64 * 36];

    const int tid = threadIdx.x, wid = tid >> 5, lane = tid & 31;
    const int qr = lane >> 2, qc = lane & 3;
    const int bh = blockIdx.y, q0 = blockIdx.x * 64;
    const uint32_t* qb = (const uint32_t*)(g_qh + (size_t)bh * N_ * D_);
    const __half* kbh = g_kh + (size_t)bh * N_ * D_;
    const __half* vbh = g_vh + (size_t)bh * N_ * D_;

#pragma unroll
    for (int r = 0; r < 16; r++) {
        int idx = tid + 128 * r; int row = idx >> 5, w = idx & 31;
        Qs[row * 36 + w] = qb[(q0 + row) * 32 + w];
    }

    auto issue = [&](int kt, int buf) {
#pragma unroll
        for (int it = 0; it < 8; it++) {
            int cid = tid + 128 * it;
            int tsel = cid >> 9, r = (cid >> 3) & 63, cc = cid & 7;
            const __half* src = (tsel ? vbh : kbh) + (size_t)(kt * 64 + r) * 64 + cc * 8;
            cpa16(smem_u32(&KV[buf][tsel][r * 36 + cc * 4]), src);
        }
        asm volatile("cp.async.commit_group;" ::: "memory");
    };
    issue(0, 0);
    __syncthreads();

    uint32_t aq[4][4];
#pragma unroll
    for (int kc = 0; kc < 4; kc++) {
        aq[kc][0] = Qs[(wid * 16 + qr) * 36 + kc * 8 + qc];
        aq[kc][1] = Qs[(wid * 16 + qr + 8) * 36 + kc * 8 + qc];
        aq[kc][2] = Qs[(wid * 16 + qr) * 36 + kc * 8 + 4 + qc];
        aq[kc][3] = Qs[(wid * 16 + qr + 8) * 36 + kc * 8 + 4 + qc];
    }

    float oacc[8][4] = {};
    float lsum0 = 0.0f, lsum1 = 0.0f;

    for (int kt = 0; kt < 32; kt++) {
        const int buf = kt & 1;
        asm volatile("cp.async.wait_group 0;" ::: "memory");
        __syncthreads();
        if (kt < 31) issue(kt + 1, buf ^ 1);

        const uint32_t Kbase = smem_u32(&KV[buf][0][0]);
        const uint32_t Vbase = smem_u32(&KV[buf][1][0]);

        // S = Q @ K^T in f16 accumulators (scores pre-scaled by log2e/8 via Q)
        uint32_t sp[8][2] = {};
#pragma unroll
        for (int nb = 0; nb < 8; nb++) {
            uint32_t rowb = (nb * 8 + (lane & 7)) * 144;
#pragma unroll
            for (int kcp = 0; kcp < 2; kcp++) {
                uint32_t b[4];
                ldm_x4(b, Kbase + rowb + (kcp * 32 + (lane >> 3) * 8) * 2);
                mma16816h(sp[nb], aq[2 * kcp],     b[0], b[1]);
                mma16816h(sp[nb], aq[2 * kcp + 1], b[2], b[3]);
            }
        }

        // P = 2^S in place; row-sum partials via hadd2 (exact-ish per tile)
        __half2 t0 = __floats2half2_rn(0.0f, 0.0f), t1 = t0;
#pragma unroll
        for (int nb = 0; nb < 8; nb++) {
            sp[nb][0] = ex2h2(sp[nb][0]);
            sp[nb][1] = ex2h2(sp[nb][1]);
            t0 = __hadd2(t0, *(__half2*)&sp[nb][0]);
            t1 = __hadd2(t1, *(__half2*)&sp[nb][1]);
        }
        lsum0 += __low2float(t0) + __high2float(t0);
        lsum1 += __low2float(t1) + __high2float(t1);

        // O += P @ V: A-fragment for k-chunk j = {sp[2j][0],sp[2j][1],sp[2j+1][0],sp[2j+1][1]}
#pragma unroll
        for (int nb = 0; nb < 8; nb++) {
#pragma unroll
            for (int kcp = 0; kcp < 2; kcp++) {
                uint32_t b[4];
                uint32_t row = kcp * 32 + (lane & 7) + (lane >> 3) * 8;
                ldm_x4_t(b, Vbase + row * 144 + nb * 16);
                uint32_t a0[4] = {sp[4 * kcp][0],     sp[4 * kcp][1],
                                  sp[4 * kcp + 1][0], sp[4 * kcp + 1][1]};
                uint32_t a1[4] = {sp[4 * kcp + 2][0], sp[4 * kcp + 2][1],
                                  sp[4 * kcp + 3][0], sp[4 * kcp + 3][1]};
                mma16816(oacc[nb], a0, b[0], b[1]);
                mma16816(oacc[nb], a1, b[2], b[3]);
            }
        }
    }

    // reduce row sums across the 4 lanes of each quad
    lsum0 += __shfl_xor_sync(0xffffffffu, lsum0, 1);
    lsum0 += __shfl_xor_sync(0xffffffffu, lsum0, 2);
    lsum1 += __shfl_xor_sync(0xffffffffu, lsum1, 1);
    lsum1 += __shfl_xor_sync(0xffffffffu, lsum1, 2);
    const float inv0 = 1.0f / lsum0, inv1 = 1.0f / lsum1;

    const int bi = bh >> 3, head = bh & 7;
    const int n0 = q0 + wid * 16 + qr;
#pragma unroll
    for (int nb = 0; nb < 8; nb++) {
        const int d = nb * 8 + qc * 2;
        *(__half2*)(g_ctxh + ((size_t)(bi * 2048 + n0)) * 512 + head * 64 + d) =
            __floats2half2_rn(oacc[nb][0] * inv0, oacc[nb][1] * inv0);
        *(__half2*)(g_ctxh + ((size_t)(bi * 2048 + n0 + 8)) * 512 + head * 64 + d) =
            __floats2half2_rn(oacc[nb][2] * inv1, oacc[nb][3] * inv1);
    }
}

// =====================================================================
// Kernel 3: FUSED outproj+GELU+res -> LN2 -> MLP+GELU -> +res -> out.
// =====================================================================
#define FUSED_SMEM 53248

__global__ __launch_bounds__(256) void fused_tail_kernel(
    const float* __restrict__ x, const float* __restrict__ bout,
    const float* __restrict__ g2, const float* __restrict__ be2,
    const float* __restrict__ b1, const float* __restrict__ b2,
    float* __restrict__ out)
{
    extern __shared__ __align__(16) unsigned char dynsm[];
    uint32_t* smw = (uint32_t*)dynsm;
    float* x2s = (float*)(dynsm + 36864);
    const uint32_t base = smem_u32(dynsm);
    const uint32_t ctxs_b = base, wos_b = base + 17408;
    const uint32_t y2s_b = base, hs_b = base + 9216;
    const uint32_t w1s_b = base + 18432, w2s_b = base + 27648;

    const int tid = threadIdx.x, wid = tid >> 5, lane = tid & 31;
    const int qr = lane >> 2, qc = lane & 3;
    const int mb = wid & 3, nhalf = wid >> 2;
    const int m0 = blockIdx.x * 64;

    float c[4][4] = {};
    for (int kc = 0; kc < 4; kc++) {
        __syncthreads();
#pragma unroll
        for (int it = 0; it < 4; it++) {
            int cid = tid + 256 * it;
            int row = cid >> 4, cc = cid & 15;
            cpa16(ctxs_b + (row * 68 + cc * 4) * 4,
                  g_ctxh + (size_t)(m0 + row) * 512 + kc * 128 + cc * 8);
        }
#pragma unroll
        for (int it = 0; it < 4; it++) {
            int cid = tid + 256 * it;
            int row = cid >> 4, cc = cid & 15;
            cpa16(wos_b + (row * 68 + cc * 4) * 4,
                  g_woT + (size_t)row * 512 + kc * 128 + cc * 8);
        }
        asm volatile("cp.async.commit_group;" ::: "memory");
        asm volatile("cp.async.wait_group 0;" ::: "memory");
        __syncthreads();

#pragma unroll
        for (int kp = 0; kp < 4; kp++) {
            uint32_t a0[4], a1[4];
            uint32_t arow = ctxs_b + (mb * 16 + (lane & 15)) * 272
                            + (kp * 32 + (lane >> 4) * 8) * 2;
            ldm_x4(a0, arow);
            ldm_x4(a1, arow + 32);
#pragma unroll
            for (int nb = 0; nb < 4; nb++) {
                uint32_t b[4];
                ldm_x4(b, wos_b + (nhalf * 32 + nb * 8 + (lane & 7)) * 272
                              + (kp * 32 + (lane >> 3) * 8) * 2);
                mma16816(c[nb], a0, b[0], b[1]);
                mma16816(c[nb], a1, b[2], b[3]);
            }
        }
    }
#pragma unroll
    for (int nb = 0; nb < 4; nb++) {
        int col = nhalf * 32 + nb * 8 + qc * 2;
        float bj0 = bout[col], bj1 = bout[col + 1];
#pragma unroll
        for (int hf = 0; hf < 2; hf++) {
            int row = mb * 16 + qr + hf * 8;
            float xv0 = x[(m0 + row) * 64 + col];
            float xv1 = x[(m0 + row) * 64 + col + 1];
            x2s[row * 64 + col]     = gelu(c[nb][hf * 2]     + bj0) + xv0;
            x2s[row * 64 + col + 1] = gelu(c[nb][hf * 2 + 1] + bj1) + xv1;
        }
    }
    __syncthreads();

    {
        const float g2a = g2[lane], g2b = g2[lane + 32];
        const float bea = be2[lane], beb = be2[lane + 32];
        __half* ysh = (__half*)dynsm;
#pragma unroll
        for (int rr = 0; rr < 8; rr++) {
            int row = wid * 8 + rr;
            float a = x2s[row * 64 + lane], b = x2s[row * 64 + lane + 32];
            float s = a + b;
#pragma unroll
            for (int o = 16; o; o >>= 1) s += __shfl_xor_sync(0xffffffffu, s, o);
            float mean = s * (1.0f / 64.0f);
            float da = a - mean, db = b - mean;
            float q = da * da + db * db;
#pragma unroll
            for (int o = 16; o; o >>= 1) q += __shfl_xor_sync(0xffffffffu, q, o);
            float rstd = rsqrtf(q * (1.0f / 64.0f) + EPS);
            ysh[row * 72 + lane]      = __float2half(da * rstd * g2a + bea);
            ysh[row * 72 + lane + 32] = __float2half(db * rstd * g2b + beb);
        }
    }
#pragma unroll
    for (int it = 0; it < 8; it++) {
        int cid = tid + 256 * it;
        int row = cid >> 5, w = cid & 31;
        smw[(w1s_b - base) / 4 + row * 36 + w] = ((const uint32_t*)g_w1T)[cid];
        smw[(w2s_b - base) / 4 + row * 36 + w] = ((const uint32_t*)g_w2T)[cid];
    }
    __syncthreads();

    float c2[4][4] = {};
#pragma unroll
    for (int kp = 0; kp < 2; kp++) {
        uint32_t a0[4], a1[4];
        uint32_t arow = y2s_b + (mb * 16 + (lane & 15)) * 144
                        + (kp * 32 + (lane >> 4) * 8) * 2;
        ldm_x4(a0, arow);
        ldm_x4(a1, arow + 32);
#pragma unroll
        for (int nb = 0; nb < 4; nb++) {
            uint32_t b[4];
            ldm_x4(b, w1s_b + (nhalf * 32 + nb * 8 + (lane & 7)) * 144
                          + (kp * 32 + (lane >> 3) * 8) * 2);
            mma16816(c2[nb], a0, b[0], b[1]);
            mma16816(c2[nb], a1, b[2], b[3]);
        }
    }
    {
        __half* hsh = (__half*)(dynsm + 9216);
#pragma unroll
        for (int nb = 0; nb < 4; nb++) {
            int col = nhalf * 32 + nb * 8 + qc * 2;
            float bj0 = b1[col], bj1 = b1[col + 1];
#pragma unroll
            for (int hf = 0; hf < 2; hf++) {
                int row = mb * 16 + qr + hf * 8;
                *(__half2*)(hsh + row * 72 + col) = __floats2half2_rn(
                    gelu(c2[nb][hf * 2] + bj0), gelu(c2[nb][hf * 2 + 1] + bj1));
            }
        }
    }
    __syncthreads();

    float c3[4][4] = {};
#pragma unroll
    for (int kp = 0; kp < 2; kp++) {
        uint32_t a0[4], a1[4];
        uint32_t arow = hs_b + (mb * 16 + (lane & 15)) * 144
                        + (kp * 32 + (lane >> 4) * 8) * 2;
        ldm_x4(a0, arow);
        ldm_x4(a1, arow + 32);
#pragma unroll
        for (int nb = 0; nb < 4; nb++) {
            uint32_t b[4];
            ldm_x4(b, w2s_b + (nhalf * 32 + nb * 8 + (lane & 7)) * 144
                          + (kp * 32 + (lane >> 3) * 8) * 2);
            mma16816(c3[nb], a0, b[0], b[1]);
            mma16816(c3[nb], a1, b[2], b[3]);
        }
    }
#pragma unroll
    for (int nb = 0; nb < 4; nb++) {
        int col = nhalf * 32 + nb * 8 + qc * 2;
        float bj0 = b2[col], bj1 = b2[col + 1];
#pragma unroll
        for (int hf = 0; hf < 2; hf++) {
            int row = mb * 16 + qr + hf * 8;
            out[(m0 + row) * 64 + col]     = c3[nb][hf * 2]     + bj0 + x2s[row * 64 + col];
            out[(m0 + row) * 64 + col + 1] = c3[nb][hf * 2 + 1] + bj1 + x2s[row * 64 + col + 1];
        }
    }
}

// =====================================================================
extern "C" void kernel_launch(void* const* d_in, const int* in_sizes, int n_in,
                              void* d_out, int out_size)
{
    const float* x    = (const float*)d_in[0];
    const float* g1   = (const float*)d_in[1];
    const float* be1  = (const float*)d_in[2];
    const float* Wqkv = (const float*)d_in[3];
    const float* bqkv = (const float*)d_in[4];
    const float* Wout = (const float*)d_in[5];
    const float* bout = (const float*)d_in[6];
    const float* g2   = (const float*)d_in[7];
    const float* be2  = (const float*)d_in[8];
    const float* W1   = (const float*)d_in[9];
    const float* b1   = (const float*)d_in[10];
    const float* W2   = (const float*)d_in[11];
    const float* b2   = (const float*)d_in[12];
    float* out = (float*)d_out;

    cudaFuncSetAttribute(fused_tail_kernel,
                         cudaFuncAttributeMaxDynamicSharedMemorySize, FUSED_SMEM);

    wt_kernel<<<544, 256>>>(Wqkv, Wout, W1, W2);
    ln_qkv_kernel<<<128, 128>>>(x, g1, be1, bqkv);
    attn_kernel<<<dim3(32, 32), 128>>>();
    fused_tail_kernel<<<128, 256, FUSED_SMEM>>>(x, bout, g2, be2, b1, b2, out);
}

// round 13
// speedup vs baseline: 1.1562x; 1.0243x over previous
#include <cuda_runtime.h>
#include <cuda_fp16.h>
#include <math.h>
#include <stdint.h>

// ---------------- problem constants ----------------
#define B_  4
#define N_  2048
#define C_  64
#define HS_ 512
#define H_  8
#define D_  64
#define M_  (B_*N_)
#define EPS 1e-6f
#define QSCALE 0.1803368801111144f   // log2(e)/8

#define QSZ (B_*H_*N_*D_)

// ---------------- scratch ----------------
__device__ __half g_qh[QSZ];          // [b*h][n][d], pre-scaled log2e/8
__device__ __half g_kh[QSZ];
__device__ __half g_vh[QSZ];
__device__ __half g_wT [1536 * 64];   // WqkvT fp16 [n][k]
__device__ __half g_woT[64 * 512];
__device__ __half g_w1T[64 * 64];
__device__ __half g_w2T[64 * 64];
__device__ __half g_ctxh[M_ * HS_];   // attention output fp16 (b,n,h*64+d)

__device__ __forceinline__ uint32_t smem_u32(const void* p) {
    uint32_t a;
    asm("{ .reg .u64 t; cvta.to.shared.u64 t, %1; cvt.u32.u64 %0, t; }" : "=r"(a) : "l"(p));
    return a;
}
__device__ __forceinline__ void mma16816(float c[4], const uint32_t a[4],
                                         uint32_t b0, uint32_t b1) {
    asm volatile("mma.sync.aligned.m16n8k16.row.col.f32.f16.f16.f32 "
        "{%0,%1,%2,%3}, {%4,%5,%6,%7}, {%8,%9}, {%0,%1,%2,%3};"
        : "+f"(c[0]), "+f"(c[1]), "+f"(c[2]), "+f"(c[3])
        : "r"(a[0]), "r"(a[1]), "r"(a[2]), "r"(a[3]), "r"(b0), "r"(b1));
}
// f16-accumulator HMMA
__device__ __forceinline__ void mma16816h(uint32_t c[2], const uint32_t a[4],
                                          uint32_t b0, uint32_t b1) {
    asm volatile("mma.sync.aligned.m16n8k16.row.col.f16.f16.f16.f16 "
        "{%0,%1}, {%2,%3,%4,%5}, {%6,%7}, {%0,%1};"
        : "+r"(c[0]), "+r"(c[1])
        : "r"(a[0]), "r"(a[1]), "r"(a[2]), "r"(a[3]), "r"(b0), "r"(b1));
}
__device__ __forceinline__ void ldm_x4(uint32_t r[4], uint32_t addr) {
    asm volatile("ldmatrix.sync.aligned.m8n8.x4.shared.b16 {%0,%1,%2,%3}, [%4];"
        : "=r"(r[0]), "=r"(r[1]), "=r"(r[2]), "=r"(r[3]) : "r"(addr));
}
__device__ __forceinline__ void ldm_x4_t(uint32_t r[4], uint32_t addr) {
    asm volatile("ldmatrix.sync.aligned.m8n8.x4.trans.shared.b16 {%0,%1,%2,%3}, [%4];"
        : "=r"(r[0]), "=r"(r[1]), "=r"(r[2]), "=r"(r[3]) : "r"(addr));
}
__device__ __forceinline__ uint32_t ex2h2(uint32_t x) {
    asm("ex2.approx.f16x2 %0, %0;" : "+r"(x));
    return x;
}
__device__ __forceinline__ void cpa16(uint32_t dst, const void* src) {
    asm volatile("cp.async.ca.shared.global [%0], [%1], 16;" :: "r"(dst), "l"(src) : "memory");
}
__device__ __forceinline__ float gelu(float v) {
    return 0.5f * v * (1.0f + erff(v * 0.70710678118f));
}

// =====================================================================
// Kernel 0: all weight prep (fp32 -> fp16 transposed)
// =====================================================================
__global__ __launch_bounds__(256) void wt_kernel(
    const float* __restrict__ Wqkv, const float* __restrict__ Wout,
    const float* __restrict__ W1, const float* __restrict__ W2)
{
    int idx = blockIdx.x * 256 + threadIdx.x;   // 139264 total
    if (idx < 98304) {
        int k = idx / 1536, n = idx - k * 1536;
        g_wT[n * 64 + k] = __float2half(Wqkv[idx]);
    } else if (idx < 131072) {
        int i = idx - 98304; int k = i >> 6, n = i & 63;
        g_woT[n * 512 + k] = __float2half(Wout[i]);
    } else if (idx < 135168) {
        int i = idx - 131072; int k = i >> 6, n = i & 63;
        g_w1T[n * 64 + k] = __float2half(W1[i]);
    } else {
        int i = idx - 135168; int k = i >> 6, n = i & 63;
        g_w2T[n * 64 + k] = __float2half(W2[i]);
    }
}

// =====================================================================
// Kernel 1: LN1 + QKV GEMM (fp16 mma). grid (128 m-tiles, 2 j-groups),
// 128 threads. Each CTA: LN (redundant, cheap) + 6 j-tiles of 128.
// =====================================================================
__global__ __launch_bounds__(128) void ln_qkv_kernel(
    const float* __restrict__ x, const float* __restrict__ g1,
    const float* __restrict__ be1, const float* __restrict__ bias)
{
    __shared__ __align__(16) uint32_t Ys[64 * 36];
    __shared__ __align__(16) uint32_t Ws[2][128 * 36];

    const int tid = threadIdx.x, wid = tid >> 5, lane = tid & 31;
    const int qr = lane >> 2, qc = lane & 3;
    const int m0 = blockIdx.x * 64;
    const int jt0 = blockIdx.y * 6;
    const uint32_t* wtw = (const uint32_t*)g_wT;

    auto issueW = [&](int jt, int buf) {
#pragma unroll
        for (int it = 0; it < 8; it++) {
            int cid = tid + 128 * it;               // 1024 chunks of 16B
            int row = cid >> 3, cc = cid & 7;
            cpa16(smem_u32(&Ws[buf][row * 36 + cc * 4]),
                  wtw + ((jt0 + jt) * 128 + row) * 32 + cc * 4);
        }
        asm volatile("cp.async.commit_group;" ::: "memory");
    };
    issueW(0, 0);

    {
        const float g1a = g1[lane], g1b = g1[lane + 32];
        const float bea = be1[lane], beb = be1[lane + 32];
        __half* ysh = (__half*)Ys;
#pragma unroll
        for (int rr = 0; rr < 16; rr++) {
            int row = wid * 16 + rr;
            float a = x[(m0 + row) * 64 + lane];
            float b = x[(m0 + row) * 64 + lane + 32];
            float s = a + b;
#pragma unroll
            for (int o = 16; o; o >>= 1) s += __shfl_xor_sync(0xffffffffu, s, o);
            float mean = s * (1.0f / 64.0f);
            float da = a - mean, db = b - mean;
            float q = da * da + db * db;
#pragma unroll
            for (int o = 16; o; o >>= 1) q += __shfl_xor_sync(0xffffffffu, q, o);
            float rstd = rsqrtf(q * (1.0f / 64.0f) + EPS);
            ysh[row * 72 + lane]      = __float2half(da * rstd * g1a + bea);
            ysh[row * 72 + lane + 32] = __float2half(db * rstd * g1b + beb);
        }
    }
    __syncthreads();

    const uint32_t ys_base = smem_u32(Ys);
    uint32_t a[4][4][4];
#pragma unroll
    for (int m = 0; m < 4; m++)
#pragma unroll
        for (int kc = 0; kc < 4; kc++)
            ldm_x4(a[m][kc], ys_base + (m * 16 + (lane & 15)) * 144
                              + (kc * 16 + (lane >> 4) * 8) * 2);

    for (int jt = 0; jt < 6; jt++) {
        const int buf = jt & 1;
        asm volatile("cp.async.wait_group 0;" ::: "memory");
        __syncthreads();
        if (jt < 5) issueW(jt + 1, buf ^ 1);

        const uint32_t ws_base = smem_u32(&Ws[buf][0]);
        float c[4][4][4] = {};
#pragma unroll
        for (int kcp = 0; kcp < 2; kcp++) {
#pragma unroll
            for (int nb = 0; nb < 4; nb++) {
                uint32_t b[4];
                ldm_x4(b, ws_base + (wid * 32 + nb * 8 + (lane & 7)) * 144
                              + (kcp * 32 + (lane >> 3) * 8) * 2);
#pragma unroll
                for (int m = 0; m < 4; m++) {
                    mma16816(c[m][nb], a[m][2 * kcp],     b[0], b[1]);
                    mma16816(c[m][nb], a[m][2 * kcp + 1], b[2], b[3]);
                }
            }
        }
        const int j0 = (jt0 + jt) * 128;
#pragma unroll
        for (int nb = 0; nb < 4; nb++) {
            int j = j0 + wid * 32 + nb * 8 + qc * 2;
            int sel = j >> 9, head = (j >> 6) & 7, d = j & 63;
            float bj0 = bias[j], bj1 = bias[j + 1];
            float sc = (sel == 0) ? QSCALE : 1.0f;
            __half* dst = (sel == 0) ? g_qh : (sel == 1) ? g_kh : g_vh;
#pragma unroll
            for (int m = 0; m < 4; m++) {
#pragma unroll
                for (int hf = 0; hf < 2; hf++) {
                    int gm = m0 + m * 16 + qr + hf * 8;
                    int bi = gm >> 11, n = gm & 2047;
                    float v0 = (c[m][nb][hf * 2]     + bj0) * sc;
                    float v1 = (c[m][nb][hf * 2 + 1] + bj1) * sc;
                    size_t off = ((size_t)(bi * 8 + head) * 2048 + n) * 64 + d;
                    *(__half2*)(dst + off) = __floats2half2_rn(v0, v1);
                }
            }
        }
    }
}

// =====================================================================
// Kernel 2: flash attention (proven round-10/11 core, unchanged).
// =====================================================================
__global__ __launch_bounds__(128) void attn_kernel()
{
    __shared__ __align__(16) uint32_t Qs[64 * 36];
    __shared__ __align__(16) uint32_t KV[2][2][64 * 36];

    const int tid = threadIdx.x, wid = tid >> 5, lane = tid & 31;
    const int qr = lane >> 2, qc = lane & 3;
    const int bh = blockIdx.y, q0 = blockIdx.x * 64;
    const uint32_t* qb = (const uint32_t*)(g_qh + (size_t)bh * N_ * D_);
    const __half* kbh = g_kh + (size_t)bh * N_ * D_;
    const __half* vbh = g_vh + (size_t)bh * N_ * D_;

#pragma unroll
    for (int r = 0; r < 16; r++) {
        int idx = tid + 128 * r; int row = idx >> 5, w = idx & 31;
        Qs[row * 36 + w] = qb[(q0 + row) * 32 + w];
    }

    auto issue = [&](int kt, int buf) {
#pragma unroll
        for (int it = 0; it < 8; it++) {
            int cid = tid + 128 * it;
            int tsel = cid >> 9, r = (cid >> 3) & 63, cc = cid & 7;
            const __half* src = (tsel ? vbh : kbh) + (size_t)(kt * 64 + r) * 64 + cc * 8;
            cpa16(smem_u32(&KV[buf][tsel][r * 36 + cc * 4]), src);
        }
        asm volatile("cp.async.commit_group;" ::: "memory");
    };
    issue(0, 0);
    __syncthreads();

    uint32_t aq[4][4];
#pragma unroll
    for (int kc = 0; kc < 4; kc++) {
        aq[kc][0] = Qs[(wid * 16 + qr) * 36 + kc * 8 + qc];
        aq[kc][1] = Qs[(wid * 16 + qr + 8) * 36 + kc * 8 + qc];
        aq[kc][2] = Qs[(wid * 16 + qr) * 36 + kc * 8 + 4 + qc];
        aq[kc][3] = Qs[(wid * 16 + qr + 8) * 36 + kc * 8 + 4 + qc];
    }

    float oacc[8][4] = {};
    float lsum0 = 0.0f, lsum1 = 0.0f;

    for (int kt = 0; kt < 32; kt++) {
        const int buf = kt & 1;
        asm volatile("cp.async.wait_group 0;" ::: "memory");
        __syncthreads();
        if (kt < 31) issue(kt + 1, buf ^ 1);

        const uint32_t Kbase = smem_u32(&KV[buf][0][0]);
        const uint32_t Vbase = smem_u32(&KV[buf][1][0]);

        uint32_t sp[8][2] = {};
#pragma unroll
        for (int nb = 0; nb < 8; nb++) {
            uint32_t rowb = (nb * 8 + (lane & 7)) * 144;
#pragma unroll
            for (int kcp = 0; kcp < 2; kcp++) {
                uint32_t b[4];
                ldm_x4(b, Kbase + rowb + (kcp * 32 + (lane >> 3) * 8) * 2);
                mma16816h(sp[nb], aq[2 * kcp],     b[0], b[1]);
                mma16816h(sp[nb], aq[2 * kcp + 1], b[2], b[3]);
            }
        }

        __half2 t0 = __floats2half2_rn(0.0f, 0.0f), t1 = t0;
#pragma unroll
        for (int nb = 0; nb < 8; nb++) {
            sp[nb][0] = ex2h2(sp[nb][0]);
            sp[nb][1] = ex2h2(sp[nb][1]);
            t0 = __hadd2(t0, *(__half2*)&sp[nb][0]);
            t1 = __hadd2(t1, *(__half2*)&sp[nb][1]);
        }
        lsum0 += __low2float(t0) + __high2float(t0);
        lsum1 += __low2float(t1) + __high2float(t1);

#pragma unroll
        for (int nb = 0; nb < 8; nb++) {
#pragma unroll
            for (int kcp = 0; kcp < 2; kcp++) {
                uint32_t b[4];
                uint32_t row = kcp * 32 + (lane & 7) + (lane >> 3) * 8;
                ldm_x4_t(b, Vbase + row * 144 + nb * 16);
                uint32_t a0[4] = {sp[4 * kcp][0],     sp[4 * kcp][1],
                                  sp[4 * kcp + 1][0], sp[4 * kcp + 1][1]};
                uint32_t a1[4] = {sp[4 * kcp + 2][0], sp[4 * kcp + 2][1],
                                  sp[4 * kcp + 3][0], sp[4 * kcp + 3][1]};
                mma16816(oacc[nb], a0, b[0], b[1]);
                mma16816(oacc[nb], a1, b[2], b[3]);
            }
        }
    }

    lsum0 += __shfl_xor_sync(0xffffffffu, lsum0, 1);
    lsum0 += __shfl_xor_sync(0xffffffffu, lsum0, 2);
    lsum1 += __shfl_xor_sync(0xffffffffu, lsum1, 1);
    lsum1 += __shfl_xor_sync(0xffffffffu, lsum1, 2);
    const float inv0 = 1.0f / lsum0, inv1 = 1.0f / lsum1;

    const int bi = bh >> 3, head = bh & 7;
    const int n0 = q0 + wid * 16 + qr;
#pragma unroll
    for (int nb = 0; nb < 8; nb++) {
        const int d = nb * 8 + qc * 2;
        *(__half2*)(g_ctxh + ((size_t)(bi * 2048 + n0)) * 512 + head * 64 + d) =
            __floats2half2_rn(oacc[nb][0] * inv0, oacc[nb][1] * inv0);
        *(__half2*)(g_ctxh + ((size_t)(bi * 2048 + n0 + 8)) * 512 + head * 64 + d) =
            __floats2half2_rn(oacc[nb][2] * inv1, oacc[nb][3] * inv1);
    }
}

// =====================================================================
// Kernel 3: FUSED tail. Phase A double-buffered; W1/W2 prefetched.
//   [0,17408)      ctxs[0]  (A) | y2s/hs (B/C)
//   [17408,34816)  wos[0]
//   [34816,52224)  ctxs[1]
//   [52224,69632)  wos[1]
//   [69632,86016)  x2s 64x64 f32
//   [86016,95232)  W1s
//   [95232,104448) W2s
// =====================================================================
#define FUSED_SMEM 104448

__global__ __launch_bounds__(256) void fused_tail_kernel(
    const float* __restrict__ x, const float* __restrict__ bout,
    const float* __restrict__ g2, const float* __restrict__ be2,
    const float* __restrict__ b1, const float* __restrict__ b2,
    float* __restrict__ out)
{
    extern __shared__ __align__(16) unsigned char dynsm[];
    float* x2s = (float*)(dynsm + 69632);
    const uint32_t base = smem_u32(dynsm);
    const uint32_t y2s_b = base, hs_b = base + 9216;
    const uint32_t w1s_b = base + 86016, w2s_b = base + 95232;

    const int tid = threadIdx.x, wid = tid >> 5, lane = tid & 31;
    const int qr = lane >> 2, qc = lane & 3;
    const int mb = wid & 3, nhalf = wid >> 2;
    const int m0 = blockIdx.x * 64;

    // prefetch W1/W2 (16KB = 1024 chunks of 16B) as the FIRST group
#pragma unroll
    for (int it = 0; it < 4; it++) {
        int cid = tid + 256 * it;                 // 0..1023
        int sel = cid >> 9, r = (cid >> 3) & 63, cc = cid & 7;
        uint32_t dst = (sel ? w2s_b : w1s_b) + (r * 36 + cc * 4) * 4;
        const uint32_t* src = (const uint32_t*)(sel ? g_w2T : g_w1T) + r * 32 + cc * 4;
        cpa16(dst, src);
    }
    asm volatile("cp.async.commit_group;" ::: "memory");

    auto issueA = [&](int kc, int buf) {
        uint32_t ctx_b = base + buf * 34816;
        uint32_t wo_b  = ctx_b + 17408;
#pragma unroll
        for (int it = 0; it < 4; it++) {
            int cid = tid + 256 * it;             // 1024 chunks
            int row = cid >> 4, cc = cid & 15;
            cpa16(ctx_b + (row * 68 + cc * 4) * 4,
                  g_ctxh + (size_t)(m0 + row) * 512 + kc * 128 + cc * 8);
        }
#pragma unroll
        for (int it = 0; it < 4; it++) {
            int cid = tid + 256 * it;
            int row = cid >> 4, cc = cid & 15;
            cpa16(wo_b + (row * 68 + cc * 4) * 4,
                  g_woT + (size_t)row * 512 + kc * 128 + cc * 8);
        }
        asm volatile("cp.async.commit_group;" ::: "memory");
    };
    issueA(0, 0);

    // ---------------- Phase A: outproj GEMM, double-buffered ----------
    float c[4][4] = {};
#pragma unroll
    for (int kc = 0; kc < 4; kc++) {
        const int buf = kc & 1;
        if (kc < 3) issueA(kc + 1, buf ^ 1);
        if (kc < 3) { asm volatile("cp.async.wait_group 1;" ::: "memory"); }
        else        { asm volatile("cp.async.wait_group 0;" ::: "memory"); }
        __syncthreads();

        const uint32_t ctxs_b = base + buf * 34816;
        const uint32_t wos_b  = ctxs_b + 17408;
#pragma unroll
        for (int kp = 0; kp < 4; kp++) {
            uint32_t a0[4], a1[4];
            uint32_t arow = ctxs_b + (mb * 16 + (lane & 15)) * 272
                            + (kp * 32 + (lane >> 4) * 8) * 2;
            ldm_x4(a0, arow);
            ldm_x4(a1, arow + 32);
#pragma unroll
            for (int nb = 0; nb < 4; nb++) {
                uint32_t b[4];
                ldm_x4(b, wos_b + (nhalf * 32 + nb * 8 + (lane & 7)) * 272
                              + (kp * 32 + (lane >> 3) * 8) * 2);
                mma16816(c[nb], a0, b[0], b[1]);
                mma16816(c[nb], a1, b[2], b[3]);
            }
        }
        __syncthreads();   // all warps done reading buf before rewrite
    }
    // epilogue A: +bout, GELU, +x residual -> x2s
#pragma unroll
    for (int nb = 0; nb < 4; nb++) {
        int col = nhalf * 32 + nb * 8 + qc * 2;
        float bj0 = bout[col], bj1 = bout[col + 1];
#pragma unroll
        for (int hf = 0; hf < 2; hf++) {
            int row = mb * 16 + qr + hf * 8;
            float xv0 = x[(m0 + row) * 64 + col];
            float xv1 = x[(m0 + row) * 64 + col + 1];
            x2s[row * 64 + col]     = gelu(c[nb][hf * 2]     + bj0) + xv0;
            x2s[row * 64 + col + 1] = gelu(c[nb][hf * 2 + 1] + bj1) + xv1;
        }
    }
    __syncthreads();

    // ---------------- Phase B: LN2 ----------------
    {
        const float g2a = g2[lane], g2b = g2[lane + 32];
        const float bea = be2[lane], beb = be2[lane + 32];
        __half* ysh = (__half*)dynsm;   // y2s at offset 0
#pragma unroll
        for (int rr = 0; rr < 8; rr++) {
            int row = wid * 8 + rr;
            float a = x2s[row * 64 + lane], b = x2s[row * 64 + lane + 32];
            float s = a + b;
#pragma unroll
            for (int o = 16; o; o >>= 1) s += __shfl_xor_sync(0xffffffffu, s, o);
            float mean = s * (1.0f / 64.0f);
            float da = a - mean, db = b - mean;
            float q = da * da + db * db;
#pragma unroll
            for (int o = 16; o; o >>= 1) q += __shfl_xor_sync(0xffffffffu, q, o);
            float rstd = rsqrtf(q * (1.0f / 64.0f) + EPS);
            ysh[row * 72 + lane]      = __float2half(da * rstd * g2a + bea);
            ysh[row * 72 + lane + 32] = __float2half(db * rstd * g2b + beb);
        }
    }
    __syncthreads();

    // ---------------- Phase C: MLP ----------------
    float c2[4][4] = {};
#pragma unroll
    for (int kp = 0; kp < 2; kp++) {
        uint32_t a0[4], a1[4];
        uint32_t arow = y2s_b + (mb * 16 + (lane & 15)) * 144
                        + (kp * 32 + (lane >> 4) * 8) * 2;
        ldm_x4(a0, arow);
        ldm_x4(a1, arow + 32);
#pragma unroll
        for (int nb = 0; nb < 4; nb++) {
            uint32_t b[4];
            ldm_x4(b, w1s_b + (nhalf * 32 + nb * 8 + (lane & 7)) * 144
                          + (kp * 32 + (lane >> 3) * 8) * 2);
            mma16816(c2[nb], a0, b[0], b[1]);
            mma16816(c2[nb], a1, b[2], b[3]);
        }
    }
    {
        __half* hsh = (__half*)(dynsm + 9216);
#pragma unroll
        for (int nb = 0; nb < 4; nb++) {
            int col = nhalf * 32 + nb * 8 + qc * 2;
            float bj0 = b1[col], bj1 = b1[col + 1];
#pragma unroll
            for (int hf = 0; hf < 2; hf++) {
                int row = mb * 16 + qr + hf * 8;
                *(__half2*)(hsh + row * 72 + col) = __floats2half2_rn(
                    gelu(c2[nb][hf * 2] + bj0), gelu(c2[nb][hf * 2 + 1] + bj1));
            }
        }
    }
    __syncthreads();

    float c3[4][4] = {};
#pragma unroll
    for (int kp = 0; kp < 2; kp++) {
        uint32_t a0[4], a1[4];
        uint32_t arow = hs_b + (mb * 16 + (lane & 15)) * 144
                        + (kp * 32 + (lane >> 4) * 8) * 2;
        ldm_x4(a0, arow);
        ldm_x4(a1, arow + 32);
#pragma unroll
        for (int nb = 0; nb < 4; nb++) {
            uint32_t b[4];
            ldm_x4(b, w2s_b + (nhalf * 32 + nb * 8 + (lane & 7)) * 144
                          + (kp * 32 + (lane >> 3) * 8) * 2);
            mma16816(c3[nb], a0, b[0], b[1]);
            mma16816(c3[nb], a1, b[2], b[3]);
        }
    }
#pragma unroll
    for (int nb = 0; nb < 4; nb++) {
        int col = nhalf * 32 + nb * 8 + qc * 2;
        float bj0 = b2[col], bj1 = b2[col + 1];
#pragma unroll
        for (int hf = 0; hf < 2; hf++) {
            int row = mb * 16 + qr + hf * 8;
            out[(m0 + row) * 64 + col]     = c3[nb][hf * 2]     + bj0 + x2s[row * 64 + col];
            out[(m0 + row) * 64 + col + 1] = c3[nb][hf * 2 + 1] + bj1 + x2s[row * 64 + col + 1];
        }
    }
}

// =====================================================================
extern "C" void kernel_launch(void* const* d_in, const int* in_sizes, int n_in,
                              void* d_out, int out_size)
{
    const float* x    = (const float*)d_in[0];
    const float* g1   = (const float*)d_in[1];
    const float* be1  = (const float*)d_in[2];
    const float* Wqkv = (const float*)d_in[3];
    const float* bqkv = (const float*)d_in[4];
    const float* Wout = (const float*)d_in[5];
    const float* bout = (const float*)d_in[6];
    const float* g2   = (const float*)d_in[7];
    const float* be2  = (const float*)d_in[8];
    const float* W1   = (const float*)d_in[9];
    const float* b1   = (const float*)d_in[10];
    const float* W2   = (const float*)d_in[11];
    const float* b2   = (const float*)d_in[12];
    float* out = (float*)d_out;

    cudaFuncSetAttribute(fused_tail_kernel,
                         cudaFuncAttributeMaxDynamicSharedMemorySize, FUSED_SMEM);

    wt_kernel<<<544, 256>>>(Wqkv, Wout, W1, W2);
    ln_qkv_kernel<<<dim3(128, 2), 128>>>(x, g1, be1, bqkv);
    attn_kernel<<<dim3(32, 32), 128>>>();
    fused_tail_kernel<<<128, 256, FUSED_SMEM>>>(x, bout, g2, be2, b1, b2, out);
}

// round 14
// speedup vs baseline: 1.1736x; 1.0150x over previous
#include <cuda_runtime.h>
#include <cuda_fp16.h>
#include <math.h>
#include <stdint.h>

// ---------------- problem constants ----------------
#define B_  4
#define N_  2048
#define C_  64
#define HS_ 512
#define H_  8
#define D_  64
#define M_  (B_*N_)
#define EPS 1e-6f
#define QSCALE 0.1803368801111144f   // log2(e)/8

#define QSZ (B_*H_*N_*D_)

// ---------------- scratch ----------------
__device__ __half g_qh[QSZ];          // [b*h][n][d], pre-scaled log2e/8
__device__ __half g_kh[QSZ];
__device__ __half g_vh[QSZ];
__device__ __half g_wT [1536 * 64];   // WqkvT fp16 [n][k]
__device__ __half g_woT[64 * 512];
__device__ __half g_w1T[64 * 64];
__device__ __half g_w2T[64 * 64];
__device__ __half g_ctxh[M_ * HS_];   // attention output fp16 (b,n,h*64+d)

__device__ __forceinline__ uint32_t smem_u32(const void* p) {
    uint32_t a;
    asm("{ .reg .u64 t; cvta.to.shared.u64 t, %1; cvt.u32.u64 %0, t; }" : "=r"(a) : "l"(p));
    return a;
}
__device__ __forceinline__ void mma16816(float c[4], const uint32_t a[4],
                                         uint32_t b0, uint32_t b1) {
    asm volatile("mma.sync.aligned.m16n8k16.row.col.f32.f16.f16.f32 "
        "{%0,%1,%2,%3}, {%4,%5,%6,%7}, {%8,%9}, {%0,%1,%2,%3};"
        : "+f"(c[0]), "+f"(c[1]), "+f"(c[2]), "+f"(c[3])
        : "r"(a[0]), "r"(a[1]), "r"(a[2]), "r"(a[3]), "r"(b0), "r"(b1));
}
// f16-accumulator HMMA
__device__ __forceinline__ void mma16816h(uint32_t c[2], const uint32_t a[4],
                                          uint32_t b0, uint32_t b1) {
    asm volatile("mma.sync.aligned.m16n8k16.row.col.f16.f16.f16.f16 "
        "{%0,%1}, {%2,%3,%4,%5}, {%6,%7}, {%0,%1};"
        : "+r"(c[0]), "+r"(c[1])
        : "r"(a[0]), "r"(a[1]), "r"(a[2]), "r"(a[3]), "r"(b0), "r"(b1));
}
__device__ __forceinline__ void ldm_x4(uint32_t r[4], uint32_t addr) {
    asm volatile("ldmatrix.sync.aligned.m8n8.x4.shared.b16 {%0,%1,%2,%3}, [%4];"
        : "=r"(r[0]), "=r"(r[1]), "=r"(r[2]), "=r"(r[3]) : "r"(addr));
}
__device__ __forceinline__ void ldm_x4_t(uint32_t r[4], uint32_t addr) {
    asm volatile("ldmatrix.sync.aligned.m8n8.x4.trans.shared.b16 {%0,%1,%2,%3}, [%4];"
        : "=r"(r[0]), "=r"(r[1]), "=r"(r[2]), "=r"(r[3]) : "r"(addr));
}
__device__ __forceinline__ uint32_t ex2h2(uint32_t x) {
    asm("ex2.approx.f16x2 %0, %0;" : "+r"(x));
    return x;
}
__device__ __forceinline__ void cpa16(uint32_t dst, const void* src) {
    asm volatile("cp.async.ca.shared.global [%0], [%1], 16;" :: "r"(dst), "l"(src) : "memory");
}
__device__ __forceinline__ float gelu(float v) {
    return 0.5f * v * (1.0f + erff(v * 0.70710678118f));
}

// =====================================================================
// Kernel 0: all weight prep (fp32 -> fp16 transposed)
// =====================================================================
__global__ __launch_bounds__(256) void wt_kernel(
    const float* __restrict__ Wqkv, const float* __restrict__ Wout,
    const float* __restrict__ W1, const float* __restrict__ W2)
{
    int idx = blockIdx.x * 256 + threadIdx.x;   // 139264 total
    if (idx < 98304) {
        int k = idx / 1536, n = idx - k * 1536;
        g_wT[n * 64 + k] = __float2half(Wqkv[idx]);
    } else if (idx < 131072) {
        int i = idx - 98304; int k = i >> 6, n = i & 63;
        g_woT[n * 512 + k] = __float2half(Wout[i]);
    } else if (idx < 135168) {
        int i = idx - 131072; int k = i >> 6, n = i & 63;
        g_w1T[n * 64 + k] = __float2half(W1[i]);
    } else {
        int i = idx - 135168; int k = i >> 6, n = i & 63;
        g_w2T[n * 64 + k] = __float2half(W2[i]);
    }
}

// =====================================================================
// Kernel 1: LN1 + QKV GEMM (fp16 mma). grid (128 m-tiles, 2 j-groups),
// 128 threads. Each CTA: LN (redundant, cheap) + 6 j-tiles of 128.
// =====================================================================
__global__ __launch_bounds__(128) void ln_qkv_kernel(
    const float* __restrict__ x, const float* __restrict__ g1,
    const float* __restrict__ be1, const float* __restrict__ bias)
{
    __shared__ __align__(16) uint32_t Ys[64 * 36];
    __shared__ __align__(16) uint32_t Ws[2][128 * 36];

    const int tid = threadIdx.x, wid = tid >> 5, lane = tid & 31;
    const int qr = lane >> 2, qc = lane & 3;
    const int m0 = blockIdx.x * 64;
    const int jt0 = blockIdx.y * 6;
    const uint32_t* wtw = (const uint32_t*)g_wT;

    auto issueW = [&](int jt, int buf) {
#pragma unroll
        for (int it = 0; it < 8; it++) {
            int cid = tid + 128 * it;               // 1024 chunks of 16B
            int row = cid >> 3, cc = cid & 7;
            cpa16(smem_u32(&Ws[buf][row * 36 + cc * 4]),
                  wtw + ((jt0 + jt) * 128 + row) * 32 + cc * 4);
        }
        asm volatile("cp.async.commit_group;" ::: "memory");
    };
    issueW(0, 0);

    {
        const float g1a = g1[lane], g1b = g1[lane + 32];
        const float bea = be1[lane], beb = be1[lane + 32];
        __half* ysh = (__half*)Ys;
#pragma unroll
        for (int rr = 0; rr < 16; rr++) {
            int row = wid * 16 + rr;
            float a = x[(m0 + row) * 64 + lane];
            float b = x[(m0 + row) * 64 + lane + 32];
            float s = a + b;
#pragma unroll
            for (int o = 16; o; o >>= 1) s += __shfl_xor_sync(0xffffffffu, s, o);
            float mean = s * (1.0f / 64.0f);
            float da = a - mean, db = b - mean;
            float q = da * da + db * db;
#pragma unroll
            for (int o = 16; o; o >>= 1) q += __shfl_xor_sync(0xffffffffu, q, o);
            float rstd = rsqrtf(q * (1.0f / 64.0f) + EPS);
            ysh[row * 72 + lane]      = __float2half(da * rstd * g1a + bea);
            ysh[row * 72 + lane + 32] = __float2half(db * rstd * g1b + beb);
        }
    }
    __syncthreads();

    const uint32_t ys_base = smem_u32(Ys);
    uint32_t a[4][4][4];
#pragma unroll
    for (int m = 0; m < 4; m++)
#pragma unroll
        for (int kc = 0; kc < 4; kc++)
            ldm_x4(a[m][kc], ys_base + (m * 16 + (lane & 15)) * 144
                              + (kc * 16 + (lane >> 4) * 8) * 2);

    for (int jt = 0; jt < 6; jt++) {
        const int buf = jt & 1;
        asm volatile("cp.async.wait_group 0;" ::: "memory");
        __syncthreads();
        if (jt < 5) issueW(jt + 1, buf ^ 1);

        const uint32_t ws_base = smem_u32(&Ws[buf][0]);
        float c[4][4][4] = {};
#pragma unroll
        for (int kcp = 0; kcp < 2; kcp++) {
#pragma unroll
            for (int nb = 0; nb < 4; nb++) {
                uint32_t b[4];
                ldm_x4(b, ws_base + (wid * 32 + nb * 8 + (lane & 7)) * 144
                              + (kcp * 32 + (lane >> 3) * 8) * 2);
#pragma unroll
                for (int m = 0; m < 4; m++) {
                    mma16816(c[m][nb], a[m][2 * kcp],     b[0], b[1]);
                    mma16816(c[m][nb], a[m][2 * kcp + 1], b[2], b[3]);
                }
            }
        }
        const int j0 = (jt0 + jt) * 128;
#pragma unroll
        for (int nb = 0; nb < 4; nb++) {
            int j = j0 + wid * 32 + nb * 8 + qc * 2;
            int sel = j >> 9, head = (j >> 6) & 7, d = j & 63;
            float bj0 = bias[j], bj1 = bias[j + 1];
            float sc = (sel == 0) ? QSCALE : 1.0f;
            __half* dst = (sel == 0) ? g_qh : (sel == 1) ? g_kh : g_vh;
#pragma unroll
            for (int m = 0; m < 4; m++) {
#pragma unroll
                for (int hf = 0; hf < 2; hf++) {
                    int gm = m0 + m * 16 + qr + hf * 8;
                    int bi = gm >> 11, n = gm & 2047;
                    float v0 = (c[m][nb][hf * 2]     + bj0) * sc;
                    float v1 = (c[m][nb][hf * 2 + 1] + bj1) * sc;
                    size_t off = ((size_t)(bi * 8 + head) * 2048 + n) * 64 + d;
                    *(__half2*)(dst + off) = __floats2half2_rn(v0, v1);
                }
            }
        }
    }
}

// =====================================================================
// Kernel 2: flash attention (proven core, unchanged).
// =====================================================================
__global__ __launch_bounds__(128) void attn_kernel()
{
    __shared__ __align__(16) uint32_t Qs[64 * 36];
    __shared__ __align__(16) uint32_t KV[2][2][64 * 36];

    const int tid = threadIdx.x, wid = tid >> 5, lane = tid & 31;
    const int qr = lane >> 2, qc = lane & 3;
    const int bh = blockIdx.y, q0 = blockIdx.x * 64;
    const uint32_t* qb = (const uint32_t*)(g_qh + (size_t)bh * N_ * D_);
    const __half* kbh = g_kh + (size_t)bh * N_ * D_;
    const __half* vbh = g_vh + (size_t)bh * N_ * D_;

#pragma unroll
    for (int r = 0; r < 16; r++) {
        int idx = tid + 128 * r; int row = idx >> 5, w = idx & 31;
        Qs[row * 36 + w] = qb[(q0 + row) * 32 + w];
    }

    auto issue = [&](int kt, int buf) {
#pragma unroll
        for (int it = 0; it < 8; it++) {
            int cid = tid + 128 * it;
            int tsel = cid >> 9, r = (cid >> 3) & 63, cc = cid & 7;
            const __half* src = (tsel ? vbh : kbh) + (size_t)(kt * 64 + r) * 64 + cc * 8;
            cpa16(smem_u32(&KV[buf][tsel][r * 36 + cc * 4]), src);
        }
        asm volatile("cp.async.commit_group;" ::: "memory");
    };
    issue(0, 0);
    __syncthreads();

    uint32_t aq[4][4];
#pragma unroll
    for (int kc = 0; kc < 4; kc++) {
        aq[kc][0] = Qs[(wid * 16 + qr) * 36 + kc * 8 + qc];
        aq[kc][1] = Qs[(wid * 16 + qr + 8) * 36 + kc * 8 + qc];
        aq[kc][2] = Qs[(wid * 16 + qr) * 36 + kc * 8 + 4 + qc];
        aq[kc][3] = Qs[(wid * 16 + qr + 8) * 36 + kc * 8 + 4 + qc];
    }

    float oacc[8][4] = {};
    float lsum0 = 0.0f, lsum1 = 0.0f;

    for (int kt = 0; kt < 32; kt++) {
        const int buf = kt & 1;
        asm volatile("cp.async.wait_group 0;" ::: "memory");
        __syncthreads();
        if (kt < 31) issue(kt + 1, buf ^ 1);

        const uint32_t Kbase = smem_u32(&KV[buf][0][0]);
        const uint32_t Vbase = smem_u32(&KV[buf][1][0]);

        uint32_t sp[8][2] = {};
#pragma unroll
        for (int nb = 0; nb < 8; nb++) {
            uint32_t rowb = (nb * 8 + (lane & 7)) * 144;
#pragma unroll
            for (int kcp = 0; kcp < 2; kcp++) {
                uint32_t b[4];
                ldm_x4(b, Kbase + rowb + (kcp * 32 + (lane >> 3) * 8) * 2);
                mma16816h(sp[nb], aq[2 * kcp],     b[0], b[1]);
                mma16816h(sp[nb], aq[2 * kcp + 1], b[2], b[3]);
            }
        }

        __half2 t0 = __floats2half2_rn(0.0f, 0.0f), t1 = t0;
#pragma unroll
        for (int nb = 0; nb < 8; nb++) {
            sp[nb][0] = ex2h2(sp[nb][0]);
            sp[nb][1] = ex2h2(sp[nb][1]);
            t0 = __hadd2(t0, *(__half2*)&sp[nb][0]);
            t1 = __hadd2(t1, *(__half2*)&sp[nb][1]);
        }
        lsum0 += __low2float(t0) + __high2float(t0);
        lsum1 += __low2float(t1) + __high2float(t1);

#pragma unroll
        for (int nb = 0; nb < 8; nb++) {
#pragma unroll
            for (int kcp = 0; kcp < 2; kcp++) {
                uint32_t b[4];
                uint32_t row = kcp * 32 + (lane & 7) + (lane >> 3) * 8;
                ldm_x4_t(b, Vbase + row * 144 + nb * 16);
                uint32_t a0[4] = {sp[4 * kcp][0],     sp[4 * kcp][1],
                                  sp[4 * kcp + 1][0], sp[4 * kcp + 1][1]};
                uint32_t a1[4] = {sp[4 * kcp + 2][0], sp[4 * kcp + 2][1],
                                  sp[4 * kcp + 3][0], sp[4 * kcp + 3][1]};
                mma16816(oacc[nb], a0, b[0], b[1]);
                mma16816(oacc[nb], a1, b[2], b[3]);
            }
        }
    }

    lsum0 += __shfl_xor_sync(0xffffffffu, lsum0, 1);
    lsum0 += __shfl_xor_sync(0xffffffffu, lsum0, 2);
    lsum1 += __shfl_xor_sync(0xffffffffu, lsum1, 1);
    lsum1 += __shfl_xor_sync(0xffffffffu, lsum1, 2);
    const float inv0 = 1.0f / lsum0, inv1 = 1.0f / lsum1;

    const int bi = bh >> 3, head = bh & 7;
    const int n0 = q0 + wid * 16 + qr;
#pragma unroll
    for (int nb = 0; nb < 8; nb++) {
        const int d = nb * 8 + qc * 2;
        *(__half2*)(g_ctxh + ((size_t)(bi * 2048 + n0)) * 512 + head * 64 + d) =
            __floats2half2_rn(oacc[nb][0] * inv0, oacc[nb][1] * inv0);
        *(__half2*)(g_ctxh + ((size_t)(bi * 2048 + n0 + 8)) * 512 + head * 64 + d) =
            __floats2half2_rn(oacc[nb][2] * inv1, oacc[nb][3] * inv1);
    }
}

// =====================================================================
// Kernel 3: FUSED tail, 32-row tiles for occupancy. grid 256, 256 thr
// / 8 warps: mb = wid&1 (16-row m-block), ng = wid>>1 (16-col n-group,
// 2 n-blocks of 8). Smem (bytes):
//   [0,8704)       ctx[0] 32x272B     | y2s (B/C) @0, hs @4608
//   [8704,26112)   wo[0]  64x272B
//   [26112,34816)  ctx[1]
//   [34816,52224)  wo[1]
//   [52224,60416)  x2s 32x64 f32
//   [60416,69632)  W1s 64x144B
//   [69632,78848)  W2s
// =====================================================================
#define FUSED_SMEM 78848

__global__ __launch_bounds__(256) void fused_tail_kernel(
    const float* __restrict__ x, const float* __restrict__ bout,
    const float* __restrict__ g2, const float* __restrict__ be2,
    const float* __restrict__ b1, const float* __restrict__ b2,
    float* __restrict__ out)
{
    extern __shared__ __align__(16) unsigned char dynsm[];
    float* x2s = (float*)(dynsm + 52224);
    const uint32_t base = smem_u32(dynsm);
    const uint32_t y2s_b = base, hs_b = base + 4608;
    const uint32_t w1s_b = base + 60416, w2s_b = base + 69632;

    const int tid = threadIdx.x, wid = tid >> 5, lane = tid & 31;
    const int qr = lane >> 2, qc = lane & 3;
    const int mb = wid & 1, ng = wid >> 1;
    const int m0 = blockIdx.x * 32;

    // prefetch W1/W2 (16KB = 1024 chunks of 16B) as the FIRST group
#pragma unroll
    for (int it = 0; it < 4; it++) {
        int cid = tid + 256 * it;                 // 0..1023
        int sel = cid >> 9, r = (cid >> 3) & 63, cc = cid & 7;
        uint32_t dst = (sel ? w2s_b : w1s_b) + (r * 36 + cc * 4) * 4;
        const uint32_t* src = (const uint32_t*)(sel ? g_w2T : g_w1T) + r * 32 + cc * 4;
        cpa16(dst, src);
    }
    asm volatile("cp.async.commit_group;" ::: "memory");

    auto issueA = [&](int kc, int buf) {
        uint32_t ctx_b = base + buf * 26112;
        uint32_t wo_b  = ctx_b + 8704;
        // ctx: 32 rows x 128 halves = 512 chunks
#pragma unroll
        for (int it = 0; it < 2; it++) {
            int cid = tid + 256 * it;
            int row = cid >> 4, cc = cid & 15;
            cpa16(ctx_b + (row * 68 + cc * 4) * 4,
                  g_ctxh + (size_t)(m0 + row) * 512 + kc * 128 + cc * 8);
        }
        // wo: 64 rows x 128 halves = 1024 chunks
#pragma unroll
        for (int it = 0; it < 4; it++) {
            int cid = tid + 256 * it;
            int row = cid >> 4, cc = cid & 15;
            cpa16(wo_b + (row * 68 + cc * 4) * 4,
                  g_woT + (size_t)row * 512 + kc * 128 + cc * 8);
        }
        asm volatile("cp.async.commit_group;" ::: "memory");
    };
    issueA(0, 0);

    // ---------------- Phase A: outproj GEMM (M=32), double-buffered ---
    float c[2][4] = {};
#pragma unroll
    for (int kc = 0; kc < 4; kc++) {
        const int buf = kc & 1;
        if (kc < 3) issueA(kc + 1, buf ^ 1);
        if (kc < 3) { asm volatile("cp.async.wait_group 1;" ::: "memory"); }
        else        { asm volatile("cp.async.wait_group 0;" ::: "memory"); }
        __syncthreads();

        const uint32_t ctxs_b = base + buf * 26112;
        const uint32_t wos_b  = ctxs_b + 8704;
#pragma unroll
        for (int kp = 0; kp < 4; kp++) {
            uint32_t a0[4], a1[4];
            uint32_t arow = ctxs_b + (mb * 16 + (lane & 15)) * 272
                            + (kp * 32 + (lane >> 4) * 8) * 2;
            ldm_x4(a0, arow);
            ldm_x4(a1, arow + 32);
#pragma unroll
            for (int nb = 0; nb < 2; nb++) {
                uint32_t b[4];
                ldm_x4(b, wos_b + (ng * 16 + nb * 8 + (lane & 7)) * 272
                              + (kp * 32 + (lane >> 3) * 8) * 2);
                mma16816(c[nb], a0, b[0], b[1]);
                mma16816(c[nb], a1, b[2], b[3]);
            }
        }
        __syncthreads();   // all warps done reading buf before rewrite
    }
    // epilogue A: +bout, GELU, +x residual -> x2s
#pragma unroll
    for (int nb = 0; nb < 2; nb++) {
        int col = ng * 16 + nb * 8 + qc * 2;
        float bj0 = bout[col], bj1 = bout[col + 1];
#pragma unroll
        for (int hf = 0; hf < 2; hf++) {
            int row = mb * 16 + qr + hf * 8;
            float xv0 = x[(m0 + row) * 64 + col];
            float xv1 = x[(m0 + row) * 64 + col + 1];
            x2s[row * 64 + col]     = gelu(c[nb][hf * 2]     + bj0) + xv0;
            x2s[row * 64 + col + 1] = gelu(c[nb][hf * 2 + 1] + bj1) + xv1;
        }
    }
    __syncthreads();

    // ---------------- Phase B: LN2 (32 rows, 4 rows/warp) -------------
    {
        const float g2a = g2[lane], g2b = g2[lane + 32];
        const float bea = be2[lane], beb = be2[lane + 32];
        __half* ysh = (__half*)dynsm;   // y2s at offset 0
#pragma unroll
        for (int rr = 0; rr < 4; rr++) {
            int row = wid * 4 + rr;
            float a = x2s[row * 64 + lane], b = x2s[row * 64 + lane + 32];
            float s = a + b;
#pragma unroll
            for (int o = 16; o; o >>= 1) s += __shfl_xor_sync(0xffffffffu, s, o);
            float mean = s * (1.0f / 64.0f);
            float da = a - mean, db = b - mean;
            float q = da * da + db * db;
#pragma unroll
            for (int o = 16; o; o >>= 1) q += __shfl_xor_sync(0xffffffffu, q, o);
            float rstd = rsqrtf(q * (1.0f / 64.0f) + EPS);
            ysh[row * 72 + lane]      = __float2half(da * rstd * g2a + bea);
            ysh[row * 72 + lane + 32] = __float2half(db * rstd * g2b + beb);
        }
    }
    __syncthreads();

    // ---------------- Phase C: MLP ----------------
    float c2[2][4] = {};
#pragma unroll
    for (int kp = 0; kp < 2; kp++) {
        uint32_t a0[4], a1[4];
        uint32_t arow = y2s_b + (mb * 16 + (lane & 15)) * 144
                        + (kp * 32 + (lane >> 4) * 8) * 2;
        ldm_x4(a0, arow);
        ldm_x4(a1, arow + 32);
#pragma unroll
        for (int nb = 0; nb < 2; nb++) {
            uint32_t b[4];
            ldm_x4(b, w1s_b + (ng * 16 + nb * 8 + (lane & 7)) * 144
                          + (kp * 32 + (lane >> 3) * 8) * 2);
            mma16816(c2[nb], a0, b[0], b[1]);
            mma16816(c2[nb], a1, b[2], b[3]);
        }
    }
    {
        __half* hsh = (__half*)(dynsm + 4608);
#pragma unroll
        for (int nb = 0; nb < 2; nb++) {
            int col = ng * 16 + nb * 8 + qc * 2;
            float bj0 = b1[col], bj1 = b1[col + 1];
#pragma unroll
            for (int hf = 0; hf < 2; hf++) {
                int row = mb * 16 + qr + hf * 8;
                *(__half2*)(hsh + row * 72 + col) = __floats2half2_rn(
                    gelu(c2[nb][hf * 2] + bj0), gelu(c2[nb][hf * 2 + 1] + bj1));
            }
        }
    }
    __syncthreads();

    float c3[2][4] = {};
#pragma unroll
    for (int kp = 0; kp < 2; kp++) {
        uint32_t a0[4], a1[4];
        uint32_t arow = hs_b + (mb * 16 + (lane & 15)) * 144
                        + (kp * 32 + (lane >> 4) * 8) * 2;
        ldm_x4(a0, arow);
        ldm_x4(a1, arow + 32);
#pragma unroll
        for (int nb = 0; nb < 2; nb++) {
            uint32_t b[4];
            ldm_x4(b, w2s_b + (ng * 16 + nb * 8 + (lane & 7)) * 144
                          + (kp * 32 + (lane >> 3) * 8) * 2);
            mma16816(c3[nb], a0, b[0], b[1]);
            mma16816(c3[nb], a1, b[2], b[3]);
        }
    }
#pragma unroll
    for (int nb = 0; nb < 2; nb++) {
        int col = ng * 16 + nb * 8 + qc * 2;
        float bj0 = b2[col], bj1 = b2[col + 1];
#pragma unroll
        for (int hf = 0; hf < 2; hf++) {
            int row = mb * 16 + qr + hf * 8;
            out[(m0 + row) * 64 + col]     = c3[nb][hf * 2]     + bj0 + x2s[row * 64 + col];
            out[(m0 + row) * 64 + col + 1] = c3[nb][hf * 2 + 1] + bj1 + x2s[row * 64 + col + 1];
        }
    }
}

// =====================================================================
extern "C" void kernel_launch(void* const* d_in, const int* in_sizes, int n_in,
                              void* d_out, int out_size)
{
    const float* x    = (const float*)d_in[0];
    const float* g1   = (const float*)d_in[1];
    const float* be1  = (const float*)d_in[2];
    const float* Wqkv = (const float*)d_in[3];
    const float* bqkv = (const float*)d_in[4];
    const float* Wout = (const float*)d_in[5];
    const float* bout = (const float*)d_in[6];
    const float* g2   = (const float*)d_in[7];
    const float* be2  = (const float*)d_in[8];
    const float* W1   = (const float*)d_in[9];
    const float* b1   = (const float*)d_in[10];
    const float* W2   = (const float*)d_in[11];
    const float* b2   = (const float*)d_in[12];
    float* out = (float*)d_out;

    cudaFuncSetAttribute(fused_tail_kernel,
                         cudaFuncAttributeMaxDynamicSharedMemorySize, FUSED_SMEM);

    wt_kernel<<<544, 256>>>(Wqkv, Wout, W1, W2);
    ln_qkv_kernel<<<dim3(128, 2), 128>>>(x, g1, be1, bqkv);
    attn_kernel<<<dim3(32, 32), 128>>>();
    fused_tail_kernel<<<256, 256, FUSED_SMEM>>>(x, bout, g2, be2, b1, b2, out);
}